// round 10
// baseline (speedup 1.0000x reference)
#include <cuda_runtime.h>
#include <cuda_bf16.h>
#include <cstdint>

// Problem constants (fixed by setup_inputs)
#define S_LEN 2048
#define BATCH 2
#define HID   2048
#define NHEAD 16
#define DHEAD 128
#define QKV_N (3 * HID)          // 6144
#define ROWS  (S_LEN * BATCH)    // 4096
#define MROW  (BATCH * QKV_N)    // 12288

// ---------------------------------------------------------------------------
// Scratch (no allocations allowed anywhere)
// ---------------------------------------------------------------------------
__device__ __nv_bfloat16 g_Mhi[(size_t)ROWS * QKV_N];     // mixed split hi (attention input)
__device__ __nv_bfloat16 g_Mlo[(size_t)ROWS * QKV_N];     // mixed split lo
__device__ float  g_ctx[(size_t)ROWS * HID];              // attention output fp32
__device__ int8_t g_qA1[(size_t)ROWS * HID];              // activation int8 hi word
__device__ int8_t g_qA2[(size_t)ROWS * HID];              // activation int8 lo word
__device__ float  g_sA[ROWS];                             // per-row scale
__device__ int8_t g_qWq1[(size_t)QKV_N * HID];            // qkv_w^T int8 words
__device__ int8_t g_qWq2[(size_t)QKV_N * HID];
__device__ float  g_sWq[QKV_N];
__device__ int8_t g_qWp1[(size_t)HID * HID];              // proj_w^T int8 words
__device__ int8_t g_qWp2[(size_t)HID * HID];
__device__ float  g_sWp[HID];

// ---------------------------------------------------------------------------
// PTX helpers (sm_80-era features only — must assemble for plain sm_103)
// ---------------------------------------------------------------------------
__device__ __forceinline__ uint32_t smem_u32(const void* p) {
    uint32_t a;
    asm("{ .reg .u64 t; cvta.to.shared.u64 t, %1; cvt.u32.u64 %0, t; }"
        : "=r"(a) : "l"(p));
    return a;
}

#define CP_ASYNC16(dst, src) \
    asm volatile("cp.async.cg.shared.global [%0], [%1], 16;" \
        :: "r"(dst), "l"(src))
#define CP_COMMIT() asm volatile("cp.async.commit_group;" ::: "memory")
#define CP_WAIT1()  asm volatile("cp.async.wait_group 1;" ::: "memory")
#define CP_WAIT0()  asm volatile("cp.async.wait_group 0;" ::: "memory")

__device__ __forceinline__ void ldsm4(uint32_t* r, uint32_t addr) {
    asm volatile("ldmatrix.sync.aligned.m8n8.x4.shared.b16 {%0,%1,%2,%3}, [%4];"
        : "=r"(r[0]), "=r"(r[1]), "=r"(r[2]), "=r"(r[3]) : "r"(addr));
}
__device__ __forceinline__ void ldsm4t(uint32_t* r, uint32_t addr) {
    asm volatile("ldmatrix.sync.aligned.m8n8.x4.trans.shared.b16 {%0,%1,%2,%3}, [%4];"
        : "=r"(r[0]), "=r"(r[1]), "=r"(r[2]), "=r"(r[3]) : "r"(addr));
}

__device__ __forceinline__ void mma_bf16(float* c, const uint32_t* a, const uint32_t* b) {
    asm volatile(
        "mma.sync.aligned.m16n8k16.row.col.f32.bf16.bf16.f32 "
        "{%0,%1,%2,%3}, {%4,%5,%6,%7}, {%8,%9}, {%0,%1,%2,%3};"
        : "+f"(c[0]), "+f"(c[1]), "+f"(c[2]), "+f"(c[3])
        : "r"(a[0]), "r"(a[1]), "r"(a[2]), "r"(a[3]), "r"(b[0]), "r"(b[1]));
}

__device__ __forceinline__ void mma_s8(int* c, const uint32_t* a, const uint32_t* b) {
    asm volatile(
        "mma.sync.aligned.m16n8k32.row.col.s32.s8.s8.s32 "
        "{%0,%1,%2,%3}, {%4,%5,%6,%7}, {%8,%9}, {%0,%1,%2,%3};"
        : "+r"(c[0]), "+r"(c[1]), "+r"(c[2]), "+r"(c[3])
        : "r"(a[0]), "r"(a[1]), "r"(a[2]), "r"(a[3]), "r"(b[0]), "r"(b[1]));
}

// swizzles
#define SMEM_SWIZZLE_128B(o) ((o) ^ (((o) >> 3) & 0x70))
__device__ __forceinline__ uint32_t swz256(uint32_t r, uint32_t byte) {
    return r * 256 + (byte ^ ((r & 7) << 4));
}
__device__ __forceinline__ uint32_t swz64(uint32_t r, uint32_t byte) {
    uint32_t o = r * 64 + byte;
    return o ^ ((o >> 3) & 0x30);
}

// ---------------------------------------------------------------------------
// Quantization kernels: X = s*(q1 + q2/128), s = row_absmax/127
// ---------------------------------------------------------------------------
__global__ void quant_rows_kernel(const float* __restrict__ X,
                                  int8_t* __restrict__ q1,
                                  int8_t* __restrict__ q2,
                                  float* __restrict__ scale, int K)
{
    const int row = blockIdx.x;
    const float* x = X + (size_t)row * K;
    const int tid = threadIdx.x;      // 256
    __shared__ float wmax[8];

    float v[8];
    float mx = 0.0f;
#pragma unroll
    for (int j = 0; j < 8; j++) {
        v[j] = x[j * 256 + tid];
        mx = fmaxf(mx, fabsf(v[j]));
    }
#pragma unroll
    for (int o = 16; o > 0; o >>= 1)
        mx = fmaxf(mx, __shfl_xor_sync(0xffffffffu, mx, o));
    if ((tid & 31) == 0) wmax[tid >> 5] = mx;
    __syncthreads();
    if (tid == 0) {
        float m = 0.0f;
#pragma unroll
        for (int i = 0; i < 8; i++) m = fmaxf(m, wmax[i]);
        wmax[0] = fmaxf(m, 1e-20f) / 127.0f;
    }
    __syncthreads();
    const float s = wmax[0];
    const float inv = 1.0f / s;
    if (tid == 0) scale[row] = s;
#pragma unroll
    for (int j = 0; j < 8; j++) {
        int a1 = __float2int_rn(v[j] * inv);
        float r = v[j] - (float)a1 * s;
        int a2 = __float2int_rn(r * inv * 128.0f);
        q1[(size_t)row * K + j * 256 + tid] = (int8_t)a1;
        q2[(size_t)row * K + j * 256 + tid] = (int8_t)a2;
    }
}

// per-column absmax of W[K,N] via atomic float-bits max (buffer pre-zeroed)
__global__ void col_absmax_kernel(const float* __restrict__ W,
                                  float* __restrict__ amax, int K, int N)
{
    const int n = blockIdx.x * 256 + threadIdx.x;
    const int kseg = K / gridDim.y;
    const int k0 = blockIdx.y * kseg;
    float m = 0.0f;
    for (int k = k0; k < k0 + kseg; k++)
        m = fmaxf(m, fabsf(W[(size_t)k * N + n]));
    atomicMax((unsigned int*)&amax[n], __float_as_uint(m));
}

__global__ void finalize_scale_kernel(float* __restrict__ s, int n)
{
    int i = blockIdx.x * blockDim.x + threadIdx.x;
    if (i < n) s[i] = fmaxf(s[i], 1e-20f) / 127.0f;
}

// W [K,N] fp32 -> q1/q2 int8 [N,K] (transpose + 2-word quantize)
__global__ void quant_transpose_kernel(const float* __restrict__ W,
                                       const float* __restrict__ sB,
                                       int8_t* __restrict__ q1,
                                       int8_t* __restrict__ q2,
                                       int K, int N)
{
    __shared__ float t[32][33];
    int n0 = blockIdx.x * 32, k0 = blockIdx.y * 32;
    int tx = threadIdx.x, ty = threadIdx.y;  // 32 x 8
#pragma unroll
    for (int i = 0; i < 32; i += 8)
        t[ty + i][tx] = W[(size_t)(k0 + ty + i) * N + n0 + tx];
    __syncthreads();
#pragma unroll
    for (int i = 0; i < 32; i += 8) {
        int n = n0 + ty + i;
        int k = k0 + tx;
        float s = sB[n];
        float inv = 1.0f / s;
        float v = t[tx][ty + i];   // = W[k][n]
        int a1 = __float2int_rn(v * inv);
        float r = v - (float)a1 * s;
        int a2 = __float2int_rn(r * inv * 128.0f);
        q1[(size_t)n * K + k] = (int8_t)a1;
        q2[(size_t)n * K + k] = (int8_t)a2;
    }
}

// ---------------------------------------------------------------------------
// IMMA 2-word int8 GEMM: C = A @ Bt^T (+bias), A ~ sA*(a1+a2/128), B likewise.
// C[i,j] = sA[i]*sB[j]*(acc(a1b1) + acc(a1b2+a2b1)/128)
// 512 threads / 16 warps (4x4), warp tile 32x32, BK=64 (2 k32 steps),
// 3-stage cp.async. 3 IMMA issues replace 6 bf16 issues per K=32.
// Optionally writes split-bf16 (outHi/outLo) instead of fp32 C.
// ---------------------------------------------------------------------------
#define GI_STAGE 32768                // A1|A2|B1|B2, 8KB each (128 x 64 int8)
#define GI_SMEM_BYTES (3 * GI_STAGE + 1024)

__global__ void __launch_bounds__(512, 1)
gemm_i8_kernel(int M, int N, int K,
               const int8_t* __restrict__ A1,
               const int8_t* __restrict__ A2,
               const float* __restrict__ sA,
               const int8_t* __restrict__ B1,
               const int8_t* __restrict__ B2,
               const float* __restrict__ sB,
               const float* __restrict__ bias,
               float* __restrict__ C,
               __nv_bfloat16* __restrict__ outHi,
               __nv_bfloat16* __restrict__ outLo)
{
    extern __shared__ char smraw[];
    uint32_t sraw = smem_u32(smraw);
    const uint32_t sb = (sraw + 1023u) & ~1023u;

    const int tid  = threadIdx.x;
    const int lane = tid & 31;
    const int warp = tid >> 5;        // 0..15
    const int wm = warp & 3;
    const int wn = warp >> 2;
    const int rowBase = blockIdx.y * 128;
    const int colBase = blockIdx.x * 128;

    const int nch = K >> 6;           // K/64

    auto load_stage = [&](int stage, int k0) {
        const uint32_t sBase = sb + stage * GI_STAGE;
#pragma unroll
        for (int i = 0; i < 4; i++) {
            int s = tid + i * 512;           // 0..2047 (16B chunks)
            int tIdx = s >> 9;               // 0:A1 1:A2 2:B1 3:B2
            int s2 = s & 511;
            int r = s2 >> 2, c16 = s2 & 3;
            const int8_t* src =
                (tIdx == 0) ? A1 : (tIdx == 1) ? A2 : (tIdx == 2) ? B1 : B2;
            const int rb = (tIdx < 2) ? rowBase : colBase;
            const void* g = src + (size_t)(rb + r) * K + k0 + c16 * 16;
            CP_ASYNC16(sBase + tIdx * 8192 + swz64(r, c16 * 16), g);
        }
    };

    int c0[2][4][4], c1[2][4][4];
#pragma unroll
    for (int mt = 0; mt < 2; mt++)
#pragma unroll
        for (int nt = 0; nt < 4; nt++)
#pragma unroll
            for (int j = 0; j < 4; j++) { c0[mt][nt][j] = 0; c1[mt][nt][j] = 0; }

    load_stage(0, 0);
    CP_COMMIT();
    load_stage(1, 64);
    CP_COMMIT();

    const int aRow  = wm * 32 + (lane & 15);
    const int aKoff = (lane >> 4) << 4;
    const int bRow  = wn * 32 + (lane & 7) + ((lane >> 4) << 3);
    const int bKoff = ((lane >> 3) & 1) << 4;

    for (int ch = 0; ch < nch; ch++) {
        CP_WAIT1();
        __syncthreads();
        if (ch + 2 < nch) {
            load_stage((ch + 2) % 3, (ch + 2) << 6);
            CP_COMMIT();
        } else {
            CP_COMMIT();
        }

        const uint32_t sA1 = sb + (ch % 3) * GI_STAGE;
        const uint32_t sA2 = sA1 + 8192;
        const uint32_t sB1 = sA1 + 16384;
        const uint32_t sB2 = sA1 + 24576;

#pragma unroll
        for (int ks = 0; ks < 2; ks++) {
            uint32_t aQ1[2][4], aQ2[2][4];
            const int kbA = ks * 32 + aKoff;
#pragma unroll
            for (int mt = 0; mt < 2; mt++) {
                uint32_t off = swz64(aRow + mt * 16, kbA);
                ldsm4(aQ1[mt], sA1 + off);
                ldsm4(aQ2[mt], sA2 + off);
            }
            uint32_t bQ1[2][4], bQ2[2][4];
            const int kbB = ks * 32 + bKoff;
#pragma unroll
            for (int nt = 0; nt < 2; nt++) {
                uint32_t off = swz64(bRow + nt * 16, kbB);
                ldsm4(bQ1[nt], sB1 + off);
                ldsm4(bQ2[nt], sB2 + off);
            }
            // main term a1*b1
#pragma unroll
            for (int mt = 0; mt < 2; mt++)
#pragma unroll
                for (int nt = 0; nt < 2; nt++) {
                    mma_s8(c0[mt][nt * 2],     aQ1[mt], &bQ1[nt][0]);
                    mma_s8(c0[mt][nt * 2 + 1], aQ1[mt], &bQ1[nt][2]);
                }
            // cross a1*b2
#pragma unroll
            for (int mt = 0; mt < 2; mt++)
#pragma unroll
                for (int nt = 0; nt < 2; nt++) {
                    mma_s8(c1[mt][nt * 2],     aQ1[mt], &bQ2[nt][0]);
                    mma_s8(c1[mt][nt * 2 + 1], aQ1[mt], &bQ2[nt][2]);
                }
            // cross a2*b1
#pragma unroll
            for (int mt = 0; mt < 2; mt++)
#pragma unroll
                for (int nt = 0; nt < 2; nt++) {
                    mma_s8(c1[mt][nt * 2],     aQ2[mt], &bQ1[nt][0]);
                    mma_s8(c1[mt][nt * 2 + 1], aQ2[mt], &bQ1[nt][2]);
                }
        }
    }

    const int qr = lane >> 2;
    const int qc = (lane & 3) * 2;
#pragma unroll
    for (int mt = 0; mt < 2; mt++) {
        const int row = rowBase + wm * 32 + mt * 16 + qr;
        const float sa0 = sA[row];
        const float sa1 = sA[row + 8];
#pragma unroll
        for (int nt = 0; nt < 4; nt++) {
            const int col = colBase + wn * 32 + nt * 8 + qc;
            const float sb0 = sB[col];
            const float sb1 = sB[col + 1];
            float b0 = 0.0f, b1 = 0.0f;
            if (bias) { b0 = bias[col]; b1 = bias[col + 1]; }
            float v00 = sa0 * sb0 * ((float)c0[mt][nt][0] + (float)c1[mt][nt][0] * 0.0078125f) + b0;
            float v01 = sa0 * sb1 * ((float)c0[mt][nt][1] + (float)c1[mt][nt][1] * 0.0078125f) + b1;
            float v10 = sa1 * sb0 * ((float)c0[mt][nt][2] + (float)c1[mt][nt][2] * 0.0078125f) + b0;
            float v11 = sa1 * sb1 * ((float)c0[mt][nt][3] + (float)c1[mt][nt][3] * 0.0078125f) + b1;
            if (outHi) {
                __nv_bfloat16 h00 = __float2bfloat16(v00), h01 = __float2bfloat16(v01);
                __nv_bfloat16 h10 = __float2bfloat16(v10), h11 = __float2bfloat16(v11);
                __nv_bfloat16 l00 = __float2bfloat16(v00 - __bfloat162float(h00));
                __nv_bfloat16 l01 = __float2bfloat16(v01 - __bfloat162float(h01));
                __nv_bfloat16 l10 = __float2bfloat16(v10 - __bfloat162float(h10));
                __nv_bfloat16 l11 = __float2bfloat16(v11 - __bfloat162float(h11));
                *(__nv_bfloat162*)&outHi[(size_t)row * N + col]       = __halves2bfloat162(h00, h01);
                *(__nv_bfloat162*)&outHi[(size_t)(row + 8) * N + col] = __halves2bfloat162(h10, h11);
                *(__nv_bfloat162*)&outLo[(size_t)row * N + col]       = __halves2bfloat162(l00, l01);
                *(__nv_bfloat162*)&outLo[(size_t)(row + 8) * N + col] = __halves2bfloat162(l10, l11);
            } else {
                *(float2*)&C[(size_t)row * N + col]       = make_float2(v00, v01);
                *(float2*)&C[(size_t)(row + 8) * N + col] = make_float2(v10, v11);
            }
        }
    }
}

// ---------------------------------------------------------------------------
// FA2-style HMMA flash attention (unchanged core): 128q x 64k tiles, 8 warps,
// register softmax, split-bf16 MMAs. Epilogue now writes fp32 ctx.
// ---------------------------------------------------------------------------
#define A_OQH   0
#define A_OQL   32768
#define A_OKV   65536
#define A_OMSK  196608
#define ATTN_SMEM_BYTES (212992 + 1024)

__global__ void __launch_bounds__(256, 1)
attn_mma_kernel(const __nv_bfloat16* __restrict__ Mhi,
                const __nv_bfloat16* __restrict__ Mlo,
                const unsigned char* __restrict__ mask,
                float* __restrict__ ctx)
{
    extern __shared__ char smraw[];
    uint32_t sraw = smem_u32(smraw);
    const uint32_t sb = (sraw + 1023u) & ~1023u;

    const int tid  = threadIdx.x;
    const int lane = tid & 31;
    const int warp = tid >> 5;
    const int gr   = lane >> 2;
    const int qc   = (lane & 3) * 2;

    const int qt = (gridDim.x - 1) - blockIdx.x;
    const int q0 = qt * 128;
    const int h  = blockIdx.y;
    const int b  = blockIdx.z;
    const size_t headOff = (size_t)b * QKV_N + h * (3 * DHEAD);
    const unsigned char* mb = mask + (size_t)b * S_LEN * S_LEN;

#pragma unroll
    for (int i = 0; i < 16; i++) {
        int s = tid + i * 256;
        int half = s >> 11;
        int s2 = s & 2047;
        int r = s2 >> 4, c16 = s2 & 15;
        const __nv_bfloat16* src = (half ? Mlo : Mhi) +
            (size_t)(q0 + r) * MROW + headOff + c16 * 8;
        uint32_t d = sb + (half ? A_OQL : A_OQH) + swz256(r, c16 * 16);
        CP_ASYNC16(d, src);
    }
    CP_COMMIT();

    auto issue_kv = [&](int stage, int t) {
        const int k0 = t * 64;
        const uint32_t kvb = sb + A_OKV + stage * 65536;
#pragma unroll
        for (int i = 0; i < 16; i++) {
            int s = tid + i * 256;
            int ts = s >> 10;
            int s2 = s & 1023;
            int r = s2 >> 4, c16 = s2 & 15;
            const __nv_bfloat16* src = ((ts & 1) ? Mlo : Mhi) +
                (size_t)(k0 + r) * MROW + headOff + ((ts < 2) ? DHEAD : 2 * DHEAD) + c16 * 8;
            CP_ASYNC16(kvb + ts * 16384 + swz256(r, c16 * 16), src);
        }
        const uint32_t mkb = sb + A_OMSK + stage * 8192;
#pragma unroll
        for (int i = 0; i < 2; i++) {
            int cid = tid + i * 256;
            int r = cid >> 2, c16 = cid & 3;
            const void* src = mb + (size_t)(q0 + r) * S_LEN + t * 64 + c16 * 16;
            CP_ASYNC16(mkb + r * 64 + c16 * 16, src);
        }
    };

    issue_kv(0, 0);
    CP_COMMIT();

    float accO[16][4];
#pragma unroll
    for (int nt = 0; nt < 16; nt++)
#pragma unroll
        for (int j = 0; j < 4; j++) accO[nt][j] = 0.0f;

    float m0 = -1e30f, m1 = -1e30f, l0 = 0.0f, l1 = 0.0f;
    const float scale = 0.0883883476483184405f;
    const int lr = lane & 7, mi = lane >> 3;

    const int ntiles = 2 * qt + 2;
    for (int t = 0; t < ntiles; t++) {
        const int st = t & 1;
        if (t + 1 < ntiles) issue_kv((t + 1) & 1, t + 1);
        CP_COMMIT();
        CP_WAIT1();
        __syncthreads();

        const uint32_t sKH = sb + A_OKV + st * 65536;
        const uint32_t sKL = sKH + 16384;
        const uint32_t sVH = sKH + 32768;
        const uint32_t sVL = sKH + 49152;
        const uint32_t sMsk = sb + A_OMSK + st * 8192;
        const int k0 = t * 64;

        float s_[8][4];
#pragma unroll
        for (int nt = 0; nt < 8; nt++)
#pragma unroll
            for (int j = 0; j < 4; j++) s_[nt][j] = 0.0f;

#pragma unroll
        for (int ks = 0; ks < 8; ks++) {
            uint32_t aH[4], aL[4];
            {
                uint32_t off = swz256(warp * 16 + (lane & 15),
                                      ks * 32 + ((lane >> 4) << 4));
                ldsm4(aH, sb + A_OQH + off);
                ldsm4(aL, sb + A_OQL + off);
            }
            uint32_t bH[4][4], bL[4][4];
            const uint32_t bByte = ks * 32 + (((lane >> 3) & 1) << 4);
#pragma unroll
            for (int p = 0; p < 4; p++) {
                uint32_t off = swz256(p * 16 + (lane & 7) + ((lane >> 4) << 3), bByte);
                ldsm4(bH[p], sKH + off);
                ldsm4(bL[p], sKL + off);
            }
#pragma unroll
            for (int p = 0; p < 4; p++) {
                mma_bf16(s_[p * 2],     aH, &bH[p][0]);
                mma_bf16(s_[p * 2 + 1], aH, &bH[p][2]);
            }
#pragma unroll
            for (int p = 0; p < 4; p++) {
                mma_bf16(s_[p * 2],     aH, &bL[p][0]);
                mma_bf16(s_[p * 2 + 1], aH, &bL[p][2]);
            }
#pragma unroll
            for (int p = 0; p < 4; p++) {
                mma_bf16(s_[p * 2],     aL, &bH[p][0]);
                mma_bf16(s_[p * 2 + 1], aL, &bH[p][2]);
            }
        }

        const int r0 = q0 + warp * 16 + gr;
        const int r1 = r0 + 8;
        const bool diag = (t >= 2 * qt);
#pragma unroll
        for (int nt = 0; nt < 8; nt++) {
            const int c = nt * 8 + qc;
            unsigned short mpair0, mpair1;
            asm volatile("ld.shared.u16 %0, [%1];" : "=h"(mpair0)
                         : "r"(sMsk + (warp * 16 + gr) * 64 + c));
            asm volatile("ld.shared.u16 %0, [%1];" : "=h"(mpair1)
                         : "r"(sMsk + (warp * 16 + gr + 8) * 64 + c));
            float v0 = s_[nt][0] * scale, v1 = s_[nt][1] * scale;
            float v2 = s_[nt][2] * scale, v3 = s_[nt][3] * scale;
            if (mpair0 & 0x00FF) v0 = -10000.0f;
            if (mpair0 & 0xFF00) v1 = -10000.0f;
            if (mpair1 & 0x00FF) v2 = -10000.0f;
            if (mpair1 & 0xFF00) v3 = -10000.0f;
            if (diag) {
                if (k0 + c     > r0) v0 = -10000.0f;
                if (k0 + c + 1 > r0) v1 = -10000.0f;
                if (k0 + c     > r1) v2 = -10000.0f;
                if (k0 + c + 1 > r1) v3 = -10000.0f;
            }
            s_[nt][0] = v0; s_[nt][1] = v1; s_[nt][2] = v2; s_[nt][3] = v3;
        }

        float mx0 = -1e30f, mx1 = -1e30f;
#pragma unroll
        for (int nt = 0; nt < 8; nt++) {
            mx0 = fmaxf(mx0, fmaxf(s_[nt][0], s_[nt][1]));
            mx1 = fmaxf(mx1, fmaxf(s_[nt][2], s_[nt][3]));
        }
        mx0 = fmaxf(mx0, __shfl_xor_sync(0xffffffffu, mx0, 1));
        mx0 = fmaxf(mx0, __shfl_xor_sync(0xffffffffu, mx0, 2));
        mx1 = fmaxf(mx1, __shfl_xor_sync(0xffffffffu, mx1, 1));
        mx1 = fmaxf(mx1, __shfl_xor_sync(0xffffffffu, mx1, 2));

        const float mn0 = fmaxf(m0, mx0);
        const float mn1 = fmaxf(m1, mx1);
        const float al0 = __expf(m0 - mn0);
        const float al1 = __expf(m1 - mn1);
        m0 = mn0; m1 = mn1;

        float sm0 = 0.0f, sm1 = 0.0f;
#pragma unroll
        for (int nt = 0; nt < 8; nt++) {
            float p0 = __expf(s_[nt][0] - mn0);
            float p1 = __expf(s_[nt][1] - mn0);
            float p2 = __expf(s_[nt][2] - mn1);
            float p3 = __expf(s_[nt][3] - mn1);
            sm0 += p0 + p1; sm1 += p2 + p3;
            s_[nt][0] = p0; s_[nt][1] = p1; s_[nt][2] = p2; s_[nt][3] = p3;
        }
        sm0 += __shfl_xor_sync(0xffffffffu, sm0, 1);
        sm0 += __shfl_xor_sync(0xffffffffu, sm0, 2);
        sm1 += __shfl_xor_sync(0xffffffffu, sm1, 1);
        sm1 += __shfl_xor_sync(0xffffffffu, sm1, 2);
        l0 = l0 * al0 + sm0;
        l1 = l1 * al1 + sm1;

#pragma unroll
        for (int nt = 0; nt < 16; nt++) {
            accO[nt][0] *= al0; accO[nt][1] *= al0;
            accO[nt][2] *= al1; accO[nt][3] *= al1;
        }

#pragma unroll
        for (int ks = 0; ks < 4; ks++) {
            uint32_t pH[4], pL[4];
            {
                const float* e0 = s_[2 * ks];
                const float* e1 = s_[2 * ks + 1];
                __nv_bfloat16 h00 = __float2bfloat16(e0[0]), h01 = __float2bfloat16(e0[1]);
                __nv_bfloat16 h02 = __float2bfloat16(e0[2]), h03 = __float2bfloat16(e0[3]);
                __nv_bfloat16 h10 = __float2bfloat16(e1[0]), h11 = __float2bfloat16(e1[1]);
                __nv_bfloat16 h12 = __float2bfloat16(e1[2]), h13 = __float2bfloat16(e1[3]);
                __nv_bfloat162 a0 = __halves2bfloat162(h00, h01);
                __nv_bfloat162 a1 = __halves2bfloat162(h02, h03);
                __nv_bfloat162 a2 = __halves2bfloat162(h10, h11);
                __nv_bfloat162 a3 = __halves2bfloat162(h12, h13);
                pH[0] = *(uint32_t*)&a0; pH[1] = *(uint32_t*)&a1;
                pH[2] = *(uint32_t*)&a2; pH[3] = *(uint32_t*)&a3;
                __nv_bfloat16 g00 = __float2bfloat16(e0[0] - __bfloat162float(h00));
                __nv_bfloat16 g01 = __float2bfloat16(e0[1] - __bfloat162float(h01));
                __nv_bfloat16 g02 = __float2bfloat16(e0[2] - __bfloat162float(h02));
                __nv_bfloat16 g03 = __float2bfloat16(e0[3] - __bfloat162float(h03));
                __nv_bfloat16 g10 = __float2bfloat16(e1[0] - __bfloat162float(h10));
                __nv_bfloat16 g11 = __float2bfloat16(e1[1] - __bfloat162float(h11));
                __nv_bfloat16 g12 = __float2bfloat16(e1[2] - __bfloat162float(h12));
                __nv_bfloat16 g13 = __float2bfloat16(e1[3] - __bfloat162float(h13));
                __nv_bfloat162 c0 = __halves2bfloat162(g00, g01);
                __nv_bfloat162 c1 = __halves2bfloat162(g02, g03);
                __nv_bfloat162 c2 = __halves2bfloat162(g10, g11);
                __nv_bfloat162 c3 = __halves2bfloat162(g12, g13);
                pL[0] = *(uint32_t*)&c0; pL[1] = *(uint32_t*)&c1;
                pL[2] = *(uint32_t*)&c2; pL[3] = *(uint32_t*)&c3;
            }
            const uint32_t vrow = ks * 16 + ((mi & 1) << 3) + lr;
#pragma unroll
            for (int hh = 0; hh < 2; hh++) {
                uint32_t vh[4][4], vl[4][4];
#pragma unroll
                for (int np = 0; np < 4; np++) {
                    uint32_t vbyte = (hh * 4 + np) * 32 + ((mi >> 1) << 4);
                    uint32_t off = swz256(vrow, vbyte);
                    ldsm4t(vh[np], sVH + off);
                    ldsm4t(vl[np], sVL + off);
                }
                float (*aO)[4] = &accO[hh * 8];
#pragma unroll
                for (int np = 0; np < 4; np++) {
                    mma_bf16(aO[np * 2],     pH, &vh[np][0]);
                    mma_bf16(aO[np * 2 + 1], pH, &vh[np][2]);
                }
#pragma unroll
                for (int np = 0; np < 4; np++) {
                    mma_bf16(aO[np * 2],     pH, &vl[np][0]);
                    mma_bf16(aO[np * 2 + 1], pH, &vl[np][2]);
                }
#pragma unroll
                for (int np = 0; np < 4; np++) {
                    mma_bf16(aO[np * 2],     pL, &vh[np][0]);
                    mma_bf16(aO[np * 2 + 1], pL, &vh[np][2]);
                }
            }
        }
        __syncthreads();
    }

    // ---- epilogue: O/l -> fp32 ctx (quantized by quant_rows afterwards) ----
    const float inv0 = 1.0f / l0;
    const float inv1 = 1.0f / l1;
    const int row0 = q0 + warp * 16 + gr;
    const size_t base0 = ((size_t)row0 * BATCH + b) * HID + h * DHEAD;
    const size_t base1 = ((size_t)(row0 + 8) * BATCH + b) * HID + h * DHEAD;
#pragma unroll
    for (int nt = 0; nt < 16; nt++) {
        const int col = nt * 8 + qc;
        *(float2*)&ctx[base0 + col] = make_float2(accO[nt][0] * inv0, accO[nt][1] * inv0);
        *(float2*)&ctx[base1 + col] = make_float2(accO[nt][2] * inv1, accO[nt][3] * inv1);
    }
}

__global__ void bias_tail_kernel(const float* __restrict__ proj_bias,
                                 float* __restrict__ out_tail)
{
    int i = blockIdx.x * blockDim.x + threadIdx.x;
    if (i < HID) out_tail[i] = proj_bias[i];
}

// ---------------------------------------------------------------------------
extern "C" void kernel_launch(void* const* d_in, const int* in_sizes, int n_in,
                              void* d_out, int out_size)
{
    const float* hidden      = (const float*)d_in[0];
    const unsigned char* msk = (const unsigned char*)d_in[1];
    const float* qkv_w       = (const float*)d_in[2];
    const float* qkv_b       = (const float*)d_in[3];
    const float* proj_w      = (const float*)d_in[4];
    const float* proj_b      = (const float*)d_in[5];
    float* out               = (float*)d_out;

    __nv_bfloat16 *mHi, *mLo;
    float *ctx, *sA, *sWq, *sWp;
    int8_t *qA1, *qA2, *qWq1, *qWq2, *qWp1, *qWp2;
    cudaGetSymbolAddress((void**)&mHi, g_Mhi);
    cudaGetSymbolAddress((void**)&mLo, g_Mlo);
    cudaGetSymbolAddress((void**)&ctx, g_ctx);
    cudaGetSymbolAddress((void**)&qA1, g_qA1);
    cudaGetSymbolAddress((void**)&qA2, g_qA2);
    cudaGetSymbolAddress((void**)&sA, g_sA);
    cudaGetSymbolAddress((void**)&qWq1, g_qWq1);
    cudaGetSymbolAddress((void**)&qWq2, g_qWq2);
    cudaGetSymbolAddress((void**)&sWq, g_sWq);
    cudaGetSymbolAddress((void**)&qWp1, g_qWp1);
    cudaGetSymbolAddress((void**)&qWp2, g_qWp2);
    cudaGetSymbolAddress((void**)&sWp, g_sWp);

    cudaFuncSetAttribute(attn_mma_kernel,
                         cudaFuncAttributeMaxDynamicSharedMemorySize, ATTN_SMEM_BYTES);
    cudaFuncSetAttribute(gemm_i8_kernel,
                         cudaFuncAttributeMaxDynamicSharedMemorySize, GI_SMEM_BYTES);

    // 0) Weight scales (atomic absmax) + quantize-transpose; activation quant
    cudaMemsetAsync(sWq, 0, QKV_N * sizeof(float));
    cudaMemsetAsync(sWp, 0, HID * sizeof(float));
    col_absmax_kernel<<<dim3(QKV_N / 256, 16), 256>>>(qkv_w, sWq, HID, QKV_N);
    col_absmax_kernel<<<dim3(HID / 256, 16), 256>>>(proj_w, sWp, HID, HID);
    finalize_scale_kernel<<<(QKV_N + 255) / 256, 256>>>(sWq, QKV_N);
    finalize_scale_kernel<<<(HID + 255) / 256, 256>>>(sWp, HID);
    {
        dim3 blk(32, 8);
        quant_transpose_kernel<<<dim3(QKV_N / 32, HID / 32), blk>>>(qkv_w, sWq, qWq1, qWq2, HID, QKV_N);
        quant_transpose_kernel<<<dim3(HID / 32, HID / 32), blk>>>(proj_w, sWp, qWp1, qWp2, HID, HID);
    }
    quant_rows_kernel<<<ROWS, 256>>>(hidden, qA1, qA2, sA, HID);

    // 1) QKV GEMM (int8 IMMA) -> split-bf16 mixed for attention
    {
        dim3 grid(QKV_N / 128, ROWS / 128);
        gemm_i8_kernel<<<grid, 512, GI_SMEM_BYTES>>>(ROWS, QKV_N, HID,
                                                     qA1, qA2, sA, qWq1, qWq2, sWq,
                                                     qkv_b, nullptr, mHi, mLo);
    }
    // 2) FA2 HMMA attention -> fp32 ctx
    {
        dim3 grid(S_LEN / 128, NHEAD, BATCH);
        attn_mma_kernel<<<grid, 256, ATTN_SMEM_BYTES>>>(mHi, mLo, msk, ctx);
    }
    // 3) Quantize ctx rows, then projection (int8 IMMA) -> fp32 out
    quant_rows_kernel<<<ROWS, 256>>>(ctx, qA1, qA2, sA, HID);
    {
        dim3 grid(HID / 128, ROWS / 128);
        gemm_i8_kernel<<<grid, 512, GI_SMEM_BYTES>>>(ROWS, HID, HID,
                                                     qA1, qA2, sA, qWp1, qWp2, sWp,
                                                     (const float*)nullptr, out,
                                                     nullptr, nullptr);
    }
    // 4) Tail: proj_bias after main output
    bias_tail_kernel<<<(HID + 255) / 256, 256>>>(proj_b, out + (size_t)ROWS * HID);
}

// round 11
// speedup vs baseline: 2.7312x; 2.7312x over previous
#include <cuda_runtime.h>
#include <cuda_fp16.h>
#include <cstdint>

// Problem constants (fixed by setup_inputs)
#define S_LEN 2048
#define BATCH 2
#define HID   2048
#define NHEAD 16
#define DHEAD 128
#define QKV_N (3 * HID)          // 6144
#define ROWS  (S_LEN * BATCH)    // 4096
#define MROW  (BATCH * QKV_N)    // 12288

// ---------------------------------------------------------------------------
// Scratch (no allocations allowed anywhere)
// ---------------------------------------------------------------------------
__device__ __half g_Mhi[(size_t)ROWS * QKV_N];     // mixed split hi
__device__ __half g_Mlo[(size_t)ROWS * QKV_N];     // mixed split lo
__device__ __half g_Ahi[(size_t)ROWS * HID];       // activation split (hidden, then ctx)
__device__ __half g_Alo[(size_t)ROWS * HID];
__device__ __half g_WqT_hi[(size_t)QKV_N * HID];   // qkv_w^T [6144,2048]
__device__ __half g_WqT_lo[(size_t)QKV_N * HID];
__device__ __half g_WpT_hi[(size_t)HID * HID];     // proj_w^T [2048,2048]
__device__ __half g_WpT_lo[(size_t)HID * HID];

// ---------------------------------------------------------------------------
// PTX helpers (sm_80-era features only — must assemble for plain sm_103)
// ---------------------------------------------------------------------------
__device__ __forceinline__ uint32_t smem_u32(const void* p) {
    uint32_t a;
    asm("{ .reg .u64 t; cvta.to.shared.u64 t, %1; cvt.u32.u64 %0, t; }"
        : "=r"(a) : "l"(p));
    return a;
}

#define CP_ASYNC16(dst, src) \
    asm volatile("cp.async.cg.shared.global [%0], [%1], 16;" \
        :: "r"(dst), "l"(src))
#define CP_COMMIT() asm volatile("cp.async.commit_group;" ::: "memory")
#define CP_WAIT1()  asm volatile("cp.async.wait_group 1;" ::: "memory")
#define CP_WAIT0()  asm volatile("cp.async.wait_group 0;" ::: "memory")

__device__ __forceinline__ void ldsm4(uint32_t* r, uint32_t addr) {
    asm volatile("ldmatrix.sync.aligned.m8n8.x4.shared.b16 {%0,%1,%2,%3}, [%4];"
        : "=r"(r[0]), "=r"(r[1]), "=r"(r[2]), "=r"(r[3]) : "r"(addr));
}
__device__ __forceinline__ void ldsm4t(uint32_t* r, uint32_t addr) {
    asm volatile("ldmatrix.sync.aligned.m8n8.x4.trans.shared.b16 {%0,%1,%2,%3}, [%4];"
        : "=r"(r[0]), "=r"(r[1]), "=r"(r[2]), "=r"(r[3]) : "r"(addr));
}

__device__ __forceinline__ void mma_f16(float* c, const uint32_t* a, const uint32_t* b) {
    asm volatile(
        "mma.sync.aligned.m16n8k16.row.col.f32.f16.f16.f32 "
        "{%0,%1,%2,%3}, {%4,%5,%6,%7}, {%8,%9}, {%0,%1,%2,%3};"
        : "+f"(c[0]), "+f"(c[1]), "+f"(c[2]), "+f"(c[3])
        : "r"(a[0]), "r"(a[1]), "r"(a[2]), "r"(a[3]), "r"(b[0]), "r"(b[1]));
}

#define SMEM_SWIZZLE_128B(o) ((o) ^ (((o) >> 3) & 0x70))
// swizzle for tiles with 256-byte rows (128 fp16): XOR 16B-chunk idx with row%8
__device__ __forceinline__ uint32_t swz256(uint32_t r, uint32_t byte) {
    return r * 256 + (byte ^ ((r & 7) << 4));
}

// fp16 hi/lo split helpers
__device__ __forceinline__ void split2(float v, __half& h, __half& l) {
    h = __float2half_rn(v);
    l = __float2half_rn(v - __half2float(h));
}

// ---------------------------------------------------------------------------
// Conversion kernels
// ---------------------------------------------------------------------------
__global__ void split_kernel(const float* __restrict__ X,
                             __half* __restrict__ hi,
                             __half* __restrict__ lo, int n4)
{
    int i = blockIdx.x * blockDim.x + threadIdx.x;
    if (i >= n4) return;
    float4 v = ((const float4*)X)[i];
    __half h0, h1, h2, h3, l0, l1, l2, l3;
    split2(v.x, h0, l0); split2(v.y, h1, l1);
    split2(v.z, h2, l2); split2(v.w, h3, l3);
    ((__half2*)hi)[i * 2]     = __halves2half2(h0, h1);
    ((__half2*)hi)[i * 2 + 1] = __halves2half2(h2, h3);
    ((__half2*)lo)[i * 2]     = __halves2half2(l0, l1);
    ((__half2*)lo)[i * 2 + 1] = __halves2half2(l2, l3);
}

// W [K,N] fp32 -> hi/lo [N,K] fp16 (transpose + split)
__global__ void transpose_split_kernel(const float* __restrict__ W,
                                       __half* __restrict__ hi,
                                       __half* __restrict__ lo,
                                       int K, int N)
{
    __shared__ float t[32][33];
    int n0 = blockIdx.x * 32, k0 = blockIdx.y * 32;
    int tx = threadIdx.x, ty = threadIdx.y;  // 32 x 8
#pragma unroll
    for (int i = 0; i < 32; i += 8)
        t[ty + i][tx] = W[(size_t)(k0 + ty + i) * N + n0 + tx];
    __syncthreads();
#pragma unroll
    for (int i = 0; i < 32; i += 8) {
        int n = n0 + ty + i;
        int k = k0 + tx;
        float v = t[tx][ty + i];   // = W[k][n]
        __half h, l;
        split2(v, h, l);
        hi[(size_t)n * K + k] = h;
        lo[(size_t)n * K + k] = l;
    }
}

// ---------------------------------------------------------------------------
// HMMA split-fp16 GEMM: C = A @ Bt^T (+bias).
// THREE=true: 3-term (Ah*Bh + Ah*Bl + Al*Bh) ~ fp32-exact.
// THREE=false: 2-term (Ah*Bh + Ah*Bl), err ~2.8e-4 — for the last GEMM only.
// 512 threads / 16 warps (4x4), warp tile 32x32, BK=64, 3-stage cp.async.
// ---------------------------------------------------------------------------
#define G_STAGE 65536                 // Ahi|Alo|Bhi|Blo, 16KB each
#define G_SMEM_BYTES (3 * G_STAGE + 1024)

template <bool THREE>
__global__ void __launch_bounds__(512, 1)
gemm_mma_kernel(int M, int N, int K,
                const __half* __restrict__ Ahi,
                const __half* __restrict__ Alo,
                const __half* __restrict__ Bhi,
                const __half* __restrict__ Blo,
                const float* __restrict__ bias,
                float* __restrict__ C,
                __half* __restrict__ outHi,
                __half* __restrict__ outLo)
{
    extern __shared__ char smraw[];
    uint32_t sraw = smem_u32(smraw);
    const uint32_t sb = (sraw + 1023u) & ~1023u;

    const int tid  = threadIdx.x;
    const int lane = tid & 31;
    const int warp = tid >> 5;        // 0..15
    const int wm = warp & 3;
    const int wn = warp >> 2;
    const int rowBase = blockIdx.y * 128;
    const int colBase = blockIdx.x * 128;

    const int nch = K >> 6;

    auto load_stage = [&](int stage, int k0) {
        const uint32_t sBase = sb + stage * G_STAGE;
#pragma unroll
        for (int tIdx = 0; tIdx < 4; tIdx++) {
            const __half* src =
                (tIdx == 0) ? Ahi : (tIdx == 1) ? Alo : (tIdx == 2) ? Bhi : Blo;
            const int rb = (tIdx < 2) ? rowBase : colBase;
#pragma unroll
            for (int i = 0; i < 2; i++) {
                int s = tid + i * 512;       // 0..1023
                int r = s >> 3, c16 = s & 7;
                const void* g = src + (size_t)(rb + r) * K + k0 + c16 * 8;
                uint32_t d = sBase + tIdx * 16384 + SMEM_SWIZZLE_128B(r * 128 + c16 * 16);
                CP_ASYNC16(d, g);
            }
        }
    };

    float c[2][4][4];
#pragma unroll
    for (int mt = 0; mt < 2; mt++)
#pragma unroll
        for (int nt = 0; nt < 4; nt++)
#pragma unroll
            for (int j = 0; j < 4; j++) c[mt][nt][j] = 0.0f;

    load_stage(0, 0);
    CP_COMMIT();
    load_stage(1, 64);
    CP_COMMIT();

    const int aRow  = wm * 32 + (lane & 15);
    const int aKoff = (lane >> 4) << 4;
    const int bRow  = wn * 32 + (lane & 7) + ((lane >> 4) << 3);
    const int bKoff = ((lane >> 3) & 1) << 4;

    for (int ch = 0; ch < nch; ch++) {
        CP_WAIT1();
        __syncthreads();
        if (ch + 2 < nch) {
            load_stage((ch + 2) % 3, (ch + 2) << 6);
            CP_COMMIT();
        } else {
            CP_COMMIT();
        }

        const uint32_t sA_hi = sb + (ch % 3) * G_STAGE;
        const uint32_t sA_lo = sA_hi + 16384;
        const uint32_t sB_hi = sA_hi + 32768;
        const uint32_t sB_lo = sA_hi + 49152;

#pragma unroll
        for (int ks = 0; ks < 4; ks++) {
            uint32_t aH[2][4], aL[2][4];
            const int kbA = ks * 32 + aKoff;
#pragma unroll
            for (int mt = 0; mt < 2; mt++) {
                uint32_t off = SMEM_SWIZZLE_128B((aRow + mt * 16) * 128 + kbA);
                ldsm4(aH[mt], sA_hi + off);
                if (THREE) ldsm4(aL[mt], sA_lo + off);
            }
            uint32_t bH[2][4], bL[2][4];
            const int kbB = ks * 32 + bKoff;
#pragma unroll
            for (int nt = 0; nt < 2; nt++) {
                uint32_t off = SMEM_SWIZZLE_128B((bRow + nt * 16) * 128 + kbB);
                ldsm4(bH[nt], sB_hi + off);
                ldsm4(bL[nt], sB_lo + off);
            }
            // term-major issue order
#pragma unroll
            for (int mt = 0; mt < 2; mt++)
#pragma unroll
                for (int nt = 0; nt < 2; nt++) {
                    mma_f16(c[mt][nt * 2],     aH[mt], &bH[nt][0]);
                    mma_f16(c[mt][nt * 2 + 1], aH[mt], &bH[nt][2]);
                }
#pragma unroll
            for (int mt = 0; mt < 2; mt++)
#pragma unroll
                for (int nt = 0; nt < 2; nt++) {
                    mma_f16(c[mt][nt * 2],     aH[mt], &bL[nt][0]);
                    mma_f16(c[mt][nt * 2 + 1], aH[mt], &bL[nt][2]);
                }
            if (THREE) {
#pragma unroll
                for (int mt = 0; mt < 2; mt++)
#pragma unroll
                    for (int nt = 0; nt < 2; nt++) {
                        mma_f16(c[mt][nt * 2],     aL[mt], &bH[nt][0]);
                        mma_f16(c[mt][nt * 2 + 1], aL[mt], &bH[nt][2]);
                    }
            }
        }
    }

    const int qr = lane >> 2;
    const int qc = (lane & 3) * 2;
#pragma unroll
    for (int mt = 0; mt < 2; mt++) {
        const int row = rowBase + wm * 32 + mt * 16 + qr;
#pragma unroll
        for (int nt = 0; nt < 4; nt++) {
            const int col = colBase + wn * 32 + nt * 8 + qc;
            float b0 = 0.0f, b1 = 0.0f;
            if (bias) { b0 = bias[col]; b1 = bias[col + 1]; }
            float v00 = c[mt][nt][0] + b0, v01 = c[mt][nt][1] + b1;
            float v10 = c[mt][nt][2] + b0, v11 = c[mt][nt][3] + b1;
            if (outHi) {
                __half h00, h01, h10, h11, l00, l01, l10, l11;
                split2(v00, h00, l00); split2(v01, h01, l01);
                split2(v10, h10, l10); split2(v11, h11, l11);
                *(__half2*)&outHi[(size_t)row * N + col]       = __halves2half2(h00, h01);
                *(__half2*)&outHi[(size_t)(row + 8) * N + col] = __halves2half2(h10, h11);
                *(__half2*)&outLo[(size_t)row * N + col]       = __halves2half2(l00, l01);
                *(__half2*)&outLo[(size_t)(row + 8) * N + col] = __halves2half2(l10, l11);
            } else {
                *(float2*)&C[(size_t)row * N + col]       = make_float2(v00, v01);
                *(float2*)&C[(size_t)(row + 8) * N + col] = make_float2(v10, v11);
            }
        }
    }
}

// ---------------------------------------------------------------------------
// FA2-style HMMA flash attention: 128q x 64k tiles, 8 warps x 16 rows each,
// register softmax, P from regs. QK^T 3-term fp16 (exact scores);
// P·V 2-term (pH·vh + pH·vl — P-lo dropped, err ~2.8e-4 direct).
// ---------------------------------------------------------------------------
#define A_OQH   0
#define A_OQL   32768
#define A_OKV   65536
#define A_OMSK  196608
#define ATTN_SMEM_BYTES (212992 + 1024)

__global__ void __launch_bounds__(256, 1)
attn_mma_kernel(const __half* __restrict__ Mhi,
                const __half* __restrict__ Mlo,
                const unsigned char* __restrict__ mask,
                __half* __restrict__ ctxHi,
                __half* __restrict__ ctxLo)
{
    extern __shared__ char smraw[];
    uint32_t sraw = smem_u32(smraw);
    const uint32_t sb = (sraw + 1023u) & ~1023u;

    const int tid  = threadIdx.x;
    const int lane = tid & 31;
    const int warp = tid >> 5;
    const int gr   = lane >> 2;
    const int qc   = (lane & 3) * 2;

    const int qt = (gridDim.x - 1) - blockIdx.x;
    const int q0 = qt * 128;
    const int h  = blockIdx.y;
    const int b  = blockIdx.z;
    const size_t headOff = (size_t)b * QKV_N + h * (3 * DHEAD);
    const unsigned char* mb = mask + (size_t)b * S_LEN * S_LEN;

#pragma unroll
    for (int i = 0; i < 16; i++) {
        int s = tid + i * 256;
        int half_ = s >> 11;
        int s2 = s & 2047;
        int r = s2 >> 4, c16 = s2 & 15;
        const __half* src = (half_ ? Mlo : Mhi) +
            (size_t)(q0 + r) * MROW + headOff + c16 * 8;
        uint32_t d = sb + (half_ ? A_OQL : A_OQH) + swz256(r, c16 * 16);
        CP_ASYNC16(d, src);
    }
    CP_COMMIT();

    auto issue_kv = [&](int stage, int t) {
        const int k0 = t * 64;
        const uint32_t kvb = sb + A_OKV + stage * 65536;
#pragma unroll
        for (int i = 0; i < 16; i++) {
            int s = tid + i * 256;
            int ts = s >> 10;
            int s2 = s & 1023;
            int r = s2 >> 4, c16 = s2 & 15;
            const __half* src = ((ts & 1) ? Mlo : Mhi) +
                (size_t)(k0 + r) * MROW + headOff + ((ts < 2) ? DHEAD : 2 * DHEAD) + c16 * 8;
            CP_ASYNC16(kvb + ts * 16384 + swz256(r, c16 * 16), src);
        }
        const uint32_t mkb = sb + A_OMSK + stage * 8192;
#pragma unroll
        for (int i = 0; i < 2; i++) {
            int cid = tid + i * 256;
            int r = cid >> 2, c16 = cid & 3;
            const void* src = mb + (size_t)(q0 + r) * S_LEN + t * 64 + c16 * 16;
            CP_ASYNC16(mkb + r * 64 + c16 * 16, src);
        }
    };

    issue_kv(0, 0);
    CP_COMMIT();

    float accO[16][4];
#pragma unroll
    for (int nt = 0; nt < 16; nt++)
#pragma unroll
        for (int j = 0; j < 4; j++) accO[nt][j] = 0.0f;

    float m0 = -1e30f, m1 = -1e30f, l0 = 0.0f, l1 = 0.0f;
    const float scale = 0.0883883476483184405f;
    const int lr = lane & 7, mi = lane >> 3;

    const int ntiles = 2 * qt + 2;
    for (int t = 0; t < ntiles; t++) {
        const int st = t & 1;
        if (t + 1 < ntiles) issue_kv((t + 1) & 1, t + 1);
        CP_COMMIT();
        CP_WAIT1();
        __syncthreads();

        const uint32_t sKH = sb + A_OKV + st * 65536;
        const uint32_t sKL = sKH + 16384;
        const uint32_t sVH = sKH + 32768;
        const uint32_t sVL = sKH + 49152;
        const uint32_t sMsk = sb + A_OMSK + st * 8192;
        const int k0 = t * 64;

        // ================= QK^T (3-term fp16) =================
        float s_[8][4];
#pragma unroll
        for (int nt = 0; nt < 8; nt++)
#pragma unroll
            for (int j = 0; j < 4; j++) s_[nt][j] = 0.0f;

#pragma unroll
        for (int ks = 0; ks < 8; ks++) {
            uint32_t aH[4], aL[4];
            {
                uint32_t off = swz256(warp * 16 + (lane & 15),
                                      ks * 32 + ((lane >> 4) << 4));
                ldsm4(aH, sb + A_OQH + off);
                ldsm4(aL, sb + A_OQL + off);
            }
            uint32_t bH[4][4], bL[4][4];
            const uint32_t bByte = ks * 32 + (((lane >> 3) & 1) << 4);
#pragma unroll
            for (int p = 0; p < 4; p++) {
                uint32_t off = swz256(p * 16 + (lane & 7) + ((lane >> 4) << 3), bByte);
                ldsm4(bH[p], sKH + off);
                ldsm4(bL[p], sKL + off);
            }
#pragma unroll
            for (int p = 0; p < 4; p++) {
                mma_f16(s_[p * 2],     aH, &bH[p][0]);
                mma_f16(s_[p * 2 + 1], aH, &bH[p][2]);
            }
#pragma unroll
            for (int p = 0; p < 4; p++) {
                mma_f16(s_[p * 2],     aH, &bL[p][0]);
                mma_f16(s_[p * 2 + 1], aH, &bL[p][2]);
            }
#pragma unroll
            for (int p = 0; p < 4; p++) {
                mma_f16(s_[p * 2],     aL, &bH[p][0]);
                mma_f16(s_[p * 2 + 1], aL, &bH[p][2]);
            }
        }

        // ---- scale + padding mask + (causal on diagonal tiles) ----
        const int r0 = q0 + warp * 16 + gr;
        const int r1 = r0 + 8;
        const bool diag = (t >= 2 * qt);
#pragma unroll
        for (int nt = 0; nt < 8; nt++) {
            const int c = nt * 8 + qc;
            unsigned short mpair0, mpair1;
            asm volatile("ld.shared.u16 %0, [%1];" : "=h"(mpair0)
                         : "r"(sMsk + (warp * 16 + gr) * 64 + c));
            asm volatile("ld.shared.u16 %0, [%1];" : "=h"(mpair1)
                         : "r"(sMsk + (warp * 16 + gr + 8) * 64 + c));
            float v0 = s_[nt][0] * scale, v1 = s_[nt][1] * scale;
            float v2 = s_[nt][2] * scale, v3 = s_[nt][3] * scale;
            if (mpair0 & 0x00FF) v0 = -10000.0f;
            if (mpair0 & 0xFF00) v1 = -10000.0f;
            if (mpair1 & 0x00FF) v2 = -10000.0f;
            if (mpair1 & 0xFF00) v3 = -10000.0f;
            if (diag) {
                if (k0 + c     > r0) v0 = -10000.0f;
                if (k0 + c + 1 > r0) v1 = -10000.0f;
                if (k0 + c     > r1) v2 = -10000.0f;
                if (k0 + c + 1 > r1) v3 = -10000.0f;
            }
            s_[nt][0] = v0; s_[nt][1] = v1; s_[nt][2] = v2; s_[nt][3] = v3;
        }

        // ---- row max (registers + quad shuffles) ----
        float mx0 = -1e30f, mx1 = -1e30f;
#pragma unroll
        for (int nt = 0; nt < 8; nt++) {
            mx0 = fmaxf(mx0, fmaxf(s_[nt][0], s_[nt][1]));
            mx1 = fmaxf(mx1, fmaxf(s_[nt][2], s_[nt][3]));
        }
        mx0 = fmaxf(mx0, __shfl_xor_sync(0xffffffffu, mx0, 1));
        mx0 = fmaxf(mx0, __shfl_xor_sync(0xffffffffu, mx0, 2));
        mx1 = fmaxf(mx1, __shfl_xor_sync(0xffffffffu, mx1, 1));
        mx1 = fmaxf(mx1, __shfl_xor_sync(0xffffffffu, mx1, 2));

        const float mn0 = fmaxf(m0, mx0);
        const float mn1 = fmaxf(m1, mx1);
        const float al0 = __expf(m0 - mn0);
        const float al1 = __expf(m1 - mn1);
        m0 = mn0; m1 = mn1;

        // ---- exp + row sums ----
        float sm0 = 0.0f, sm1 = 0.0f;
#pragma unroll
        for (int nt = 0; nt < 8; nt++) {
            float p0 = __expf(s_[nt][0] - mn0);
            float p1 = __expf(s_[nt][1] - mn0);
            float p2 = __expf(s_[nt][2] - mn1);
            float p3 = __expf(s_[nt][3] - mn1);
            sm0 += p0 + p1; sm1 += p2 + p3;
            s_[nt][0] = p0; s_[nt][1] = p1; s_[nt][2] = p2; s_[nt][3] = p3;
        }
        sm0 += __shfl_xor_sync(0xffffffffu, sm0, 1);
        sm0 += __shfl_xor_sync(0xffffffffu, sm0, 2);
        sm1 += __shfl_xor_sync(0xffffffffu, sm1, 1);
        sm1 += __shfl_xor_sync(0xffffffffu, sm1, 2);
        l0 = l0 * al0 + sm0;
        l1 = l1 * al1 + sm1;

        // ---- rescale accO ----
#pragma unroll
        for (int nt = 0; nt < 16; nt++) {
            accO[nt][0] *= al0; accO[nt][1] *= al0;
            accO[nt][2] *= al1; accO[nt][3] *= al1;
        }

        // ================= P @ V (2-term: pH·vh + pH·vl) =================
#pragma unroll
        for (int ks = 0; ks < 4; ks++) {
            uint32_t pH[4];
            {
                const float* e0 = s_[2 * ks];
                const float* e1 = s_[2 * ks + 1];
                __half h00 = __float2half_rn(e0[0]), h01 = __float2half_rn(e0[1]);
                __half h02 = __float2half_rn(e0[2]), h03 = __float2half_rn(e0[3]);
                __half h10 = __float2half_rn(e1[0]), h11 = __float2half_rn(e1[1]);
                __half h12 = __float2half_rn(e1[2]), h13 = __float2half_rn(e1[3]);
                __half2 a0 = __halves2half2(h00, h01);
                __half2 a1 = __halves2half2(h02, h03);
                __half2 a2 = __halves2half2(h10, h11);
                __half2 a3 = __halves2half2(h12, h13);
                pH[0] = *(uint32_t*)&a0; pH[1] = *(uint32_t*)&a1;
                pH[2] = *(uint32_t*)&a2; pH[3] = *(uint32_t*)&a3;
            }
            const uint32_t vrow = ks * 16 + ((mi & 1) << 3) + lr;
#pragma unroll
            for (int hh = 0; hh < 2; hh++) {
                uint32_t vh[4][4], vl[4][4];
#pragma unroll
                for (int np = 0; np < 4; np++) {
                    uint32_t vbyte = (hh * 4 + np) * 32 + ((mi >> 1) << 4);
                    uint32_t off = swz256(vrow, vbyte);
                    ldsm4t(vh[np], sVH + off);
                    ldsm4t(vl[np], sVL + off);
                }
                float (*aO)[4] = &accO[hh * 8];
#pragma unroll
                for (int np = 0; np < 4; np++) {
                    mma_f16(aO[np * 2],     pH, &vh[np][0]);
                    mma_f16(aO[np * 2 + 1], pH, &vh[np][2]);
                }
#pragma unroll
                for (int np = 0; np < 4; np++) {
                    mma_f16(aO[np * 2],     pH, &vl[np][0]);
                    mma_f16(aO[np * 2 + 1], pH, &vl[np][2]);
                }
            }
        }
        __syncthreads();
    }

    // ---- epilogue: O/l -> split fp16 ctx (feeds proj GEMM directly) ----
    const float inv0 = 1.0f / l0;
    const float inv1 = 1.0f / l1;
    const int row0 = q0 + warp * 16 + gr;
    const size_t base0 = ((size_t)row0 * BATCH + b) * HID + h * DHEAD;
    const size_t base1 = ((size_t)(row0 + 8) * BATCH + b) * HID + h * DHEAD;
#pragma unroll
    for (int nt = 0; nt < 16; nt++) {
        const int col = nt * 8 + qc;
        float v00 = accO[nt][0] * inv0, v01 = accO[nt][1] * inv0;
        float v10 = accO[nt][2] * inv1, v11 = accO[nt][3] * inv1;
        __half h00, h01, h10, h11, l00, l01, l10, l11;
        split2(v00, h00, l00); split2(v01, h01, l01);
        split2(v10, h10, l10); split2(v11, h11, l11);
        *(__half2*)&ctxHi[base0 + col] = __halves2half2(h00, h01);
        *(__half2*)&ctxHi[base1 + col] = __halves2half2(h10, h11);
        *(__half2*)&ctxLo[base0 + col] = __halves2half2(l00, l01);
        *(__half2*)&ctxLo[base1 + col] = __halves2half2(l10, l11);
    }
}

__global__ void bias_tail_kernel(const float* __restrict__ proj_bias,
                                 float* __restrict__ out_tail)
{
    int i = blockIdx.x * blockDim.x + threadIdx.x;
    if (i < HID) out_tail[i] = proj_bias[i];
}

// ---------------------------------------------------------------------------
extern "C" void kernel_launch(void* const* d_in, const int* in_sizes, int n_in,
                              void* d_out, int out_size)
{
    const float* hidden      = (const float*)d_in[0];
    const unsigned char* msk = (const unsigned char*)d_in[1];
    const float* qkv_w       = (const float*)d_in[2];
    const float* qkv_b       = (const float*)d_in[3];
    const float* proj_w      = (const float*)d_in[4];
    const float* proj_b      = (const float*)d_in[5];
    float* out               = (float*)d_out;

    __half *mHi, *mLo, *aHi, *aLo, *wqHi, *wqLo, *wpHi, *wpLo;
    cudaGetSymbolAddress((void**)&mHi, g_Mhi);
    cudaGetSymbolAddress((void**)&mLo, g_Mlo);
    cudaGetSymbolAddress((void**)&aHi, g_Ahi);
    cudaGetSymbolAddress((void**)&aLo, g_Alo);
    cudaGetSymbolAddress((void**)&wqHi, g_WqT_hi);
    cudaGetSymbolAddress((void**)&wqLo, g_WqT_lo);
    cudaGetSymbolAddress((void**)&wpHi, g_WpT_hi);
    cudaGetSymbolAddress((void**)&wpLo, g_WpT_lo);

    cudaFuncSetAttribute(attn_mma_kernel,
                         cudaFuncAttributeMaxDynamicSharedMemorySize, ATTN_SMEM_BYTES);
    cudaFuncSetAttribute(gemm_mma_kernel<true>,
                         cudaFuncAttributeMaxDynamicSharedMemorySize, G_SMEM_BYTES);
    cudaFuncSetAttribute(gemm_mma_kernel<false>,
                         cudaFuncAttributeMaxDynamicSharedMemorySize, G_SMEM_BYTES);

    // 0) Weight transpose + split, activation split (fp16 hi/lo)
    {
        dim3 blk(32, 8);
        transpose_split_kernel<<<dim3(QKV_N / 32, HID / 32), blk>>>(qkv_w, wqHi, wqLo, HID, QKV_N);
        transpose_split_kernel<<<dim3(HID / 32, HID / 32), blk>>>(proj_w, wpHi, wpLo, HID, HID);
        int n4 = ROWS * HID / 4;
        split_kernel<<<(n4 + 255) / 256, 256>>>(hidden, aHi, aLo, n4);
    }
    // 1) QKV GEMM (3-term fp16, ~exact) -> split-fp16 mixed
    {
        dim3 grid(QKV_N / 128, ROWS / 128);
        gemm_mma_kernel<true><<<grid, 512, G_SMEM_BYTES>>>(ROWS, QKV_N, HID,
                                                           aHi, aLo, wqHi, wqLo, qkv_b,
                                                           nullptr, mHi, mLo);
    }
    // 2) FA2 HMMA attention -> split-fp16 ctx (into proj input buffers)
    {
        dim3 grid(S_LEN / 128, NHEAD, BATCH);
        attn_mma_kernel<<<grid, 256, ATTN_SMEM_BYTES>>>(mHi, mLo, msk, aHi, aLo);
    }
    // 3) Projection (2-term fp16): out = ctx @ proj_w (fp32 out)
    {
        dim3 grid(HID / 128, ROWS / 128);
        gemm_mma_kernel<false><<<grid, 512, G_SMEM_BYTES>>>(ROWS, HID, HID,
                                                            aHi, aLo, wpHi, wpLo,
                                                            (const float*)nullptr, out,
                                                            nullptr, nullptr);
    }
    // 4) Tail: proj_bias after main output
    bias_tail_kernel<<<(HID + 255) / 256, 256>>>(proj_b, out + (size_t)ROWS * HID);
}

// round 12
// speedup vs baseline: 3.2623x; 1.1945x over previous
#include <cuda_runtime.h>
#include <cuda_fp16.h>
#include <cstdint>

// Problem constants (fixed by setup_inputs)
#define S_LEN 2048
#define BATCH 2
#define HID   2048
#define NHEAD 16
#define DHEAD 128
#define QKV_N (3 * HID)          // 6144
#define ROWS  (S_LEN * BATCH)    // 4096
#define MROW  (BATCH * QKV_N)    // 12288

// ---------------------------------------------------------------------------
// Scratch (no allocations allowed anywhere)
// ---------------------------------------------------------------------------
__device__ __half g_Mhi[(size_t)ROWS * QKV_N];     // mixed split hi
__device__ __half g_Mlo[(size_t)ROWS * QKV_N];     // mixed split lo
__device__ __half g_Ahi[(size_t)ROWS * HID];       // activation split (hidden, then ctx)
__device__ __half g_Alo[(size_t)ROWS * HID];
__device__ __half g_WqT_hi[(size_t)QKV_N * HID];   // qkv_w^T [6144,2048]
__device__ __half g_WqT_lo[(size_t)QKV_N * HID];
__device__ __half g_WpT_hi[(size_t)HID * HID];     // proj_w^T [2048,2048]
__device__ __half g_WpT_lo[(size_t)HID * HID];

// ---------------------------------------------------------------------------
// PTX helpers (sm_80-era features only — must assemble for plain sm_103)
// ---------------------------------------------------------------------------
__device__ __forceinline__ uint32_t smem_u32(const void* p) {
    uint32_t a;
    asm("{ .reg .u64 t; cvta.to.shared.u64 t, %1; cvt.u32.u64 %0, t; }"
        : "=r"(a) : "l"(p));
    return a;
}

#define CP_ASYNC16(dst, src) \
    asm volatile("cp.async.cg.shared.global [%0], [%1], 16;" \
        :: "r"(dst), "l"(src))
#define CP_COMMIT() asm volatile("cp.async.commit_group;" ::: "memory")
#define CP_WAIT1()  asm volatile("cp.async.wait_group 1;" ::: "memory")
#define CP_WAIT0()  asm volatile("cp.async.wait_group 0;" ::: "memory")

__device__ __forceinline__ void ldsm4(uint32_t* r, uint32_t addr) {
    asm volatile("ldmatrix.sync.aligned.m8n8.x4.shared.b16 {%0,%1,%2,%3}, [%4];"
        : "=r"(r[0]), "=r"(r[1]), "=r"(r[2]), "=r"(r[3]) : "r"(addr));
}
__device__ __forceinline__ void ldsm4t(uint32_t* r, uint32_t addr) {
    asm volatile("ldmatrix.sync.aligned.m8n8.x4.trans.shared.b16 {%0,%1,%2,%3}, [%4];"
        : "=r"(r[0]), "=r"(r[1]), "=r"(r[2]), "=r"(r[3]) : "r"(addr));
}

__device__ __forceinline__ void mma_f16(float* c, const uint32_t* a, const uint32_t* b) {
    asm volatile(
        "mma.sync.aligned.m16n8k16.row.col.f32.f16.f16.f32 "
        "{%0,%1,%2,%3}, {%4,%5,%6,%7}, {%8,%9}, {%0,%1,%2,%3};"
        : "+f"(c[0]), "+f"(c[1]), "+f"(c[2]), "+f"(c[3])
        : "r"(a[0]), "r"(a[1]), "r"(a[2]), "r"(a[3]), "r"(b[0]), "r"(b[1]));
}

#define SMEM_SWIZZLE_128B(o) ((o) ^ (((o) >> 3) & 0x70))
// swizzle for tiles with 256-byte rows (128 fp16): XOR 16B-chunk idx with row%8
__device__ __forceinline__ uint32_t swz256(uint32_t r, uint32_t byte) {
    return r * 256 + (byte ^ ((r & 7) << 4));
}

// fp16 hi/lo split helpers
__device__ __forceinline__ void split2(float v, __half& h, __half& l) {
    h = __float2half_rn(v);
    l = __float2half_rn(v - __half2float(h));
}

// ---------------------------------------------------------------------------
// Conversion kernels
// ---------------------------------------------------------------------------
__global__ void split_kernel(const float* __restrict__ X,
                             __half* __restrict__ hi,
                             __half* __restrict__ lo, int n4)
{
    int i = blockIdx.x * blockDim.x + threadIdx.x;
    if (i >= n4) return;
    float4 v = ((const float4*)X)[i];
    __half h0, h1, h2, h3, l0, l1, l2, l3;
    split2(v.x, h0, l0); split2(v.y, h1, l1);
    split2(v.z, h2, l2); split2(v.w, h3, l3);
    ((__half2*)hi)[i * 2]     = __halves2half2(h0, h1);
    ((__half2*)hi)[i * 2 + 1] = __halves2half2(h2, h3);
    ((__half2*)lo)[i * 2]     = __halves2half2(l0, l1);
    ((__half2*)lo)[i * 2 + 1] = __halves2half2(l2, l3);
}

// W [K,N] fp32 -> hi/lo [N,K] fp16 (transpose + split)
__global__ void transpose_split_kernel(const float* __restrict__ W,
                                       __half* __restrict__ hi,
                                       __half* __restrict__ lo,
                                       int K, int N)
{
    __shared__ float t[32][33];
    int n0 = blockIdx.x * 32, k0 = blockIdx.y * 32;
    int tx = threadIdx.x, ty = threadIdx.y;  // 32 x 8
#pragma unroll
    for (int i = 0; i < 32; i += 8)
        t[ty + i][tx] = W[(size_t)(k0 + ty + i) * N + n0 + tx];
    __syncthreads();
#pragma unroll
    for (int i = 0; i < 32; i += 8) {
        int n = n0 + ty + i;
        int k = k0 + tx;
        float v = t[tx][ty + i];   // = W[k][n]
        __half h, l;
        split2(v, h, l);
        hi[(size_t)n * K + k] = h;
        lo[(size_t)n * K + k] = l;
    }
}

// ---------------------------------------------------------------------------
// HMMA split-fp16 GEMM (2-term: Ah*Bh + Ah*Bl, err ~2.8e-4): C = A @ Bt^T.
// A-lo never loaded. 512 threads / 16 warps (4x4), warp tile 32x32, BK=64,
// 3-stage cp.async. Optionally writes split-fp16 (outHi/outLo).
// ---------------------------------------------------------------------------
#define G_STAGE 49152                 // Ahi|Bhi|Blo, 16KB each
#define G_SMEM_BYTES (3 * G_STAGE + 1024)

__global__ void __launch_bounds__(512, 1)
gemm_mma_kernel(int M, int N, int K,
                const __half* __restrict__ Ahi,
                const __half* __restrict__ Bhi,
                const __half* __restrict__ Blo,
                const float* __restrict__ bias,
                float* __restrict__ C,
                __half* __restrict__ outHi,
                __half* __restrict__ outLo)
{
    extern __shared__ char smraw[];
    uint32_t sraw = smem_u32(smraw);
    const uint32_t sb = (sraw + 1023u) & ~1023u;

    const int tid  = threadIdx.x;
    const int lane = tid & 31;
    const int warp = tid >> 5;        // 0..15
    const int wm = warp & 3;
    const int wn = warp >> 2;
    const int rowBase = blockIdx.y * 128;
    const int colBase = blockIdx.x * 128;

    const int nch = K >> 6;

    auto load_stage = [&](int stage, int k0) {
        const uint32_t sBase = sb + stage * G_STAGE;
#pragma unroll
        for (int tIdx = 0; tIdx < 3; tIdx++) {
            const __half* src = (tIdx == 0) ? Ahi : (tIdx == 1) ? Bhi : Blo;
            const int rb = (tIdx == 0) ? rowBase : colBase;
#pragma unroll
            for (int i = 0; i < 2; i++) {
                int s = tid + i * 512;       // 0..1023
                int r = s >> 3, c16 = s & 7;
                const void* g = src + (size_t)(rb + r) * K + k0 + c16 * 8;
                uint32_t d = sBase + tIdx * 16384 + SMEM_SWIZZLE_128B(r * 128 + c16 * 16);
                CP_ASYNC16(d, g);
            }
        }
    };

    float c[2][4][4];
#pragma unroll
    for (int mt = 0; mt < 2; mt++)
#pragma unroll
        for (int nt = 0; nt < 4; nt++)
#pragma unroll
            for (int j = 0; j < 4; j++) c[mt][nt][j] = 0.0f;

    load_stage(0, 0);
    CP_COMMIT();
    load_stage(1, 64);
    CP_COMMIT();

    const int aRow  = wm * 32 + (lane & 15);
    const int aKoff = (lane >> 4) << 4;
    const int bRow  = wn * 32 + (lane & 7) + ((lane >> 4) << 3);
    const int bKoff = ((lane >> 3) & 1) << 4;

    for (int ch = 0; ch < nch; ch++) {
        CP_WAIT1();
        __syncthreads();
        if (ch + 2 < nch) {
            load_stage((ch + 2) % 3, (ch + 2) << 6);
            CP_COMMIT();
        } else {
            CP_COMMIT();
        }

        const uint32_t sA_hi = sb + (ch % 3) * G_STAGE;
        const uint32_t sB_hi = sA_hi + 16384;
        const uint32_t sB_lo = sA_hi + 32768;

#pragma unroll
        for (int ks = 0; ks < 4; ks++) {
            uint32_t aH[2][4];
            const int kbA = ks * 32 + aKoff;
#pragma unroll
            for (int mt = 0; mt < 2; mt++) {
                uint32_t off = SMEM_SWIZZLE_128B((aRow + mt * 16) * 128 + kbA);
                ldsm4(aH[mt], sA_hi + off);
            }
            uint32_t bH[2][4], bL[2][4];
            const int kbB = ks * 32 + bKoff;
#pragma unroll
            for (int nt = 0; nt < 2; nt++) {
                uint32_t off = SMEM_SWIZZLE_128B((bRow + nt * 16) * 128 + kbB);
                ldsm4(bH[nt], sB_hi + off);
                ldsm4(bL[nt], sB_lo + off);
            }
            // term-major issue order
#pragma unroll
            for (int mt = 0; mt < 2; mt++)
#pragma unroll
                for (int nt = 0; nt < 2; nt++) {
                    mma_f16(c[mt][nt * 2],     aH[mt], &bH[nt][0]);
                    mma_f16(c[mt][nt * 2 + 1], aH[mt], &bH[nt][2]);
                }
#pragma unroll
            for (int mt = 0; mt < 2; mt++)
#pragma unroll
                for (int nt = 0; nt < 2; nt++) {
                    mma_f16(c[mt][nt * 2],     aH[mt], &bL[nt][0]);
                    mma_f16(c[mt][nt * 2 + 1], aH[mt], &bL[nt][2]);
                }
        }
    }

    const int qr = lane >> 2;
    const int qc = (lane & 3) * 2;
#pragma unroll
    for (int mt = 0; mt < 2; mt++) {
        const int row = rowBase + wm * 32 + mt * 16 + qr;
#pragma unroll
        for (int nt = 0; nt < 4; nt++) {
            const int col = colBase + wn * 32 + nt * 8 + qc;
            float b0 = 0.0f, b1 = 0.0f;
            if (bias) { b0 = bias[col]; b1 = bias[col + 1]; }
            float v00 = c[mt][nt][0] + b0, v01 = c[mt][nt][1] + b1;
            float v10 = c[mt][nt][2] + b0, v11 = c[mt][nt][3] + b1;
            if (outHi) {
                __half h00, h01, h10, h11, l00, l01, l10, l11;
                split2(v00, h00, l00); split2(v01, h01, l01);
                split2(v10, h10, l10); split2(v11, h11, l11);
                *(__half2*)&outHi[(size_t)row * N + col]       = __halves2half2(h00, h01);
                *(__half2*)&outHi[(size_t)(row + 8) * N + col] = __halves2half2(h10, h11);
                *(__half2*)&outLo[(size_t)row * N + col]       = __halves2half2(l00, l01);
                *(__half2*)&outLo[(size_t)(row + 8) * N + col] = __halves2half2(l10, l11);
            } else {
                *(float2*)&C[(size_t)row * N + col]       = make_float2(v00, v01);
                *(float2*)&C[(size_t)(row + 8) * N + col] = make_float2(v10, v11);
            }
        }
    }
}

// ---------------------------------------------------------------------------
// FA2-style HMMA flash attention: 128q x 64k tiles, 8 warps x 16 rows each,
// register softmax, P from regs. QK^T 2-term (Qh·Kh + Qh·Kl, Q-lo unused);
// P·V 2-term (pH·vh + pH·vl).
// ---------------------------------------------------------------------------
#define A_OQH   0                     // Q hi: 32KB (Q lo not needed)
#define A_OKV   32768                 // 2 stages x 64KB: KH|KL|VH|VL
#define A_OMSK  163840                // 2 stages x 8KB mask
#define ATTN_SMEM_BYTES (180224 + 1024)

__global__ void __launch_bounds__(256, 1)
attn_mma_kernel(const __half* __restrict__ Mhi,
                const __half* __restrict__ Mlo,
                const unsigned char* __restrict__ mask,
                __half* __restrict__ ctxHi,
                __half* __restrict__ ctxLo)
{
    extern __shared__ char smraw[];
    uint32_t sraw = smem_u32(smraw);
    const uint32_t sb = (sraw + 1023u) & ~1023u;

    const int tid  = threadIdx.x;
    const int lane = tid & 31;
    const int warp = tid >> 5;
    const int gr   = lane >> 2;
    const int qc   = (lane & 3) * 2;

    const int qt = (gridDim.x - 1) - blockIdx.x;
    const int q0 = qt * 128;
    const int h  = blockIdx.y;
    const int b  = blockIdx.z;
    const size_t headOff = (size_t)b * QKV_N + h * (3 * DHEAD);
    const unsigned char* mb = mask + (size_t)b * S_LEN * S_LEN;

    // ---- issue Q-hi loads only (2-term QK^T) ----
#pragma unroll
    for (int i = 0; i < 8; i++) {
        int s = tid + i * 256;          // 0..2047
        int r = s >> 4, c16 = s & 15;
        const __half* src = Mhi + (size_t)(q0 + r) * MROW + headOff + c16 * 8;
        CP_ASYNC16(sb + A_OQH + swz256(r, c16 * 16), src);
    }
    CP_COMMIT();

    auto issue_kv = [&](int stage, int t) {
        const int k0 = t * 64;
        const uint32_t kvb = sb + A_OKV + stage * 65536;
#pragma unroll
        for (int i = 0; i < 16; i++) {
            int s = tid + i * 256;
            int ts = s >> 10;           // 0:KH 1:KL 2:VH 3:VL
            int s2 = s & 1023;
            int r = s2 >> 4, c16 = s2 & 15;
            const __half* src = ((ts & 1) ? Mlo : Mhi) +
                (size_t)(k0 + r) * MROW + headOff + ((ts < 2) ? DHEAD : 2 * DHEAD) + c16 * 8;
            CP_ASYNC16(kvb + ts * 16384 + swz256(r, c16 * 16), src);
        }
        const uint32_t mkb = sb + A_OMSK + stage * 8192;
#pragma unroll
        for (int i = 0; i < 2; i++) {
            int cid = tid + i * 256;
            int r = cid >> 2, c16 = cid & 3;
            const void* src = mb + (size_t)(q0 + r) * S_LEN + t * 64 + c16 * 16;
            CP_ASYNC16(mkb + r * 64 + c16 * 16, src);
        }
    };

    issue_kv(0, 0);
    CP_COMMIT();

    float accO[16][4];
#pragma unroll
    for (int nt = 0; nt < 16; nt++)
#pragma unroll
        for (int j = 0; j < 4; j++) accO[nt][j] = 0.0f;

    float m0 = -1e30f, m1 = -1e30f, l0 = 0.0f, l1 = 0.0f;
    const float scale = 0.0883883476483184405f;
    const int lr = lane & 7, mi = lane >> 3;

    const int ntiles = 2 * qt + 2;
    for (int t = 0; t < ntiles; t++) {
        const int st = t & 1;
        if (t + 1 < ntiles) issue_kv((t + 1) & 1, t + 1);
        CP_COMMIT();
        CP_WAIT1();
        __syncthreads();

        const uint32_t sKH = sb + A_OKV + st * 65536;
        const uint32_t sKL = sKH + 16384;
        const uint32_t sVH = sKH + 32768;
        const uint32_t sVL = sKH + 49152;
        const uint32_t sMsk = sb + A_OMSK + st * 8192;
        const int k0 = t * 64;

        // ================= QK^T (2-term: Qh·Kh + Qh·Kl) =================
        float s_[8][4];
#pragma unroll
        for (int nt = 0; nt < 8; nt++)
#pragma unroll
            for (int j = 0; j < 4; j++) s_[nt][j] = 0.0f;

#pragma unroll
        for (int ks = 0; ks < 8; ks++) {
            uint32_t aH[4];
            {
                uint32_t off = swz256(warp * 16 + (lane & 15),
                                      ks * 32 + ((lane >> 4) << 4));
                ldsm4(aH, sb + A_OQH + off);
            }
            uint32_t bH[4][4], bL[4][4];
            const uint32_t bByte = ks * 32 + (((lane >> 3) & 1) << 4);
#pragma unroll
            for (int p = 0; p < 4; p++) {
                uint32_t off = swz256(p * 16 + (lane & 7) + ((lane >> 4) << 3), bByte);
                ldsm4(bH[p], sKH + off);
                ldsm4(bL[p], sKL + off);
            }
#pragma unroll
            for (int p = 0; p < 4; p++) {
                mma_f16(s_[p * 2],     aH, &bH[p][0]);
                mma_f16(s_[p * 2 + 1], aH, &bH[p][2]);
            }
#pragma unroll
            for (int p = 0; p < 4; p++) {
                mma_f16(s_[p * 2],     aH, &bL[p][0]);
                mma_f16(s_[p * 2 + 1], aH, &bL[p][2]);
            }
        }

        // ---- scale + padding mask + (causal on diagonal tiles) ----
        const int r0 = q0 + warp * 16 + gr;
        const int r1 = r0 + 8;
        const bool diag = (t >= 2 * qt);
#pragma unroll
        for (int nt = 0; nt < 8; nt++) {
            const int c = nt * 8 + qc;
            unsigned short mpair0, mpair1;
            asm volatile("ld.shared.u16 %0, [%1];" : "=h"(mpair0)
                         : "r"(sMsk + (warp * 16 + gr) * 64 + c));
            asm volatile("ld.shared.u16 %0, [%1];" : "=h"(mpair1)
                         : "r"(sMsk + (warp * 16 + gr + 8) * 64 + c));
            float v0 = s_[nt][0] * scale, v1 = s_[nt][1] * scale;
            float v2 = s_[nt][2] * scale, v3 = s_[nt][3] * scale;
            if (mpair0 & 0x00FF) v0 = -10000.0f;
            if (mpair0 & 0xFF00) v1 = -10000.0f;
            if (mpair1 & 0x00FF) v2 = -10000.0f;
            if (mpair1 & 0xFF00) v3 = -10000.0f;
            if (diag) {
                if (k0 + c     > r0) v0 = -10000.0f;
                if (k0 + c + 1 > r0) v1 = -10000.0f;
                if (k0 + c     > r1) v2 = -10000.0f;
                if (k0 + c + 1 > r1) v3 = -10000.0f;
            }
            s_[nt][0] = v0; s_[nt][1] = v1; s_[nt][2] = v2; s_[nt][3] = v3;
        }

        // ---- row max (registers + quad shuffles) ----
        float mx0 = -1e30f, mx1 = -1e30f;
#pragma unroll
        for (int nt = 0; nt < 8; nt++) {
            mx0 = fmaxf(mx0, fmaxf(s_[nt][0], s_[nt][1]));
            mx1 = fmaxf(mx1, fmaxf(s_[nt][2], s_[nt][3]));
        }
        mx0 = fmaxf(mx0, __shfl_xor_sync(0xffffffffu, mx0, 1));
        mx0 = fmaxf(mx0, __shfl_xor_sync(0xffffffffu, mx0, 2));
        mx1 = fmaxf(mx1, __shfl_xor_sync(0xffffffffu, mx1, 1));
        mx1 = fmaxf(mx1, __shfl_xor_sync(0xffffffffu, mx1, 2));

        const float mn0 = fmaxf(m0, mx0);
        const float mn1 = fmaxf(m1, mx1);
        const float al0 = __expf(m0 - mn0);
        const float al1 = __expf(m1 - mn1);
        m0 = mn0; m1 = mn1;

        // ---- exp + row sums ----
        float sm0 = 0.0f, sm1 = 0.0f;
#pragma unroll
        for (int nt = 0; nt < 8; nt++) {
            float p0 = __expf(s_[nt][0] - mn0);
            float p1 = __expf(s_[nt][1] - mn0);
            float p2 = __expf(s_[nt][2] - mn1);
            float p3 = __expf(s_[nt][3] - mn1);
            sm0 += p0 + p1; sm1 += p2 + p3;
            s_[nt][0] = p0; s_[nt][1] = p1; s_[nt][2] = p2; s_[nt][3] = p3;
        }
        sm0 += __shfl_xor_sync(0xffffffffu, sm0, 1);
        sm0 += __shfl_xor_sync(0xffffffffu, sm0, 2);
        sm1 += __shfl_xor_sync(0xffffffffu, sm1, 1);
        sm1 += __shfl_xor_sync(0xffffffffu, sm1, 2);
        l0 = l0 * al0 + sm0;
        l1 = l1 * al1 + sm1;

        // ---- rescale accO ----
#pragma unroll
        for (int nt = 0; nt < 16; nt++) {
            accO[nt][0] *= al0; accO[nt][1] *= al0;
            accO[nt][2] *= al1; accO[nt][3] *= al1;
        }

        // ================= P @ V (2-term: pH·vh + pH·vl) =================
#pragma unroll
        for (int ks = 0; ks < 4; ks++) {
            uint32_t pH[4];
            {
                const float* e0 = s_[2 * ks];
                const float* e1 = s_[2 * ks + 1];
                __half h00 = __float2half_rn(e0[0]), h01 = __float2half_rn(e0[1]);
                __half h02 = __float2half_rn(e0[2]), h03 = __float2half_rn(e0[3]);
                __half h10 = __float2half_rn(e1[0]), h11 = __float2half_rn(e1[1]);
                __half h12 = __float2half_rn(e1[2]), h13 = __float2half_rn(e1[3]);
                __half2 a0 = __halves2half2(h00, h01);
                __half2 a1 = __halves2half2(h02, h03);
                __half2 a2 = __halves2half2(h10, h11);
                __half2 a3 = __halves2half2(h12, h13);
                pH[0] = *(uint32_t*)&a0; pH[1] = *(uint32_t*)&a1;
                pH[2] = *(uint32_t*)&a2; pH[3] = *(uint32_t*)&a3;
            }
            const uint32_t vrow = ks * 16 + ((mi & 1) << 3) + lr;
#pragma unroll
            for (int hh = 0; hh < 2; hh++) {
                uint32_t vh[4][4], vl[4][4];
#pragma unroll
                for (int np = 0; np < 4; np++) {
                    uint32_t vbyte = (hh * 4 + np) * 32 + ((mi >> 1) << 4);
                    uint32_t off = swz256(vrow, vbyte);
                    ldsm4t(vh[np], sVH + off);
                    ldsm4t(vl[np], sVL + off);
                }
                float (*aO)[4] = &accO[hh * 8];
#pragma unroll
                for (int np = 0; np < 4; np++) {
                    mma_f16(aO[np * 2],     pH, &vh[np][0]);
                    mma_f16(aO[np * 2 + 1], pH, &vh[np][2]);
                }
#pragma unroll
                for (int np = 0; np < 4; np++) {
                    mma_f16(aO[np * 2],     pH, &vl[np][0]);
                    mma_f16(aO[np * 2 + 1], pH, &vl[np][2]);
                }
            }
        }
        __syncthreads();
    }

    // ---- epilogue: O/l -> split fp16 ctx (feeds proj GEMM directly) ----
    const float inv0 = 1.0f / l0;
    const float inv1 = 1.0f / l1;
    const int row0 = q0 + warp * 16 + gr;
    const size_t base0 = ((size_t)row0 * BATCH + b) * HID + h * DHEAD;
    const size_t base1 = ((size_t)(row0 + 8) * BATCH + b) * HID + h * DHEAD;
#pragma unroll
    for (int nt = 0; nt < 16; nt++) {
        const int col = nt * 8 + qc;
        float v00 = accO[nt][0] * inv0, v01 = accO[nt][1] * inv0;
        float v10 = accO[nt][2] * inv1, v11 = accO[nt][3] * inv1;
        __half h00, h01, h10, h11, l00, l01, l10, l11;
        split2(v00, h00, l00); split2(v01, h01, l01);
        split2(v10, h10, l10); split2(v11, h11, l11);
        *(__half2*)&ctxHi[base0 + col] = __halves2half2(h00, h01);
        *(__half2*)&ctxHi[base1 + col] = __halves2half2(h10, h11);
        *(__half2*)&ctxLo[base0 + col] = __halves2half2(l00, l01);
        *(__half2*)&ctxLo[base1 + col] = __halves2half2(l10, l11);
    }
}

__global__ void bias_tail_kernel(const float* __restrict__ proj_bias,
                                 float* __restrict__ out_tail)
{
    int i = blockIdx.x * blockDim.x + threadIdx.x;
    if (i < HID) out_tail[i] = proj_bias[i];
}

// ---------------------------------------------------------------------------
extern "C" void kernel_launch(void* const* d_in, const int* in_sizes, int n_in,
                              void* d_out, int out_size)
{
    const float* hidden      = (const float*)d_in[0];
    const unsigned char* msk = (const unsigned char*)d_in[1];
    const float* qkv_w       = (const float*)d_in[2];
    const float* qkv_b       = (const float*)d_in[3];
    const float* proj_w      = (const float*)d_in[4];
    const float* proj_b      = (const float*)d_in[5];
    float* out               = (float*)d_out;

    __half *mHi, *mLo, *aHi, *aLo, *wqHi, *wqLo, *wpHi, *wpLo;
    cudaGetSymbolAddress((void**)&mHi, g_Mhi);
    cudaGetSymbolAddress((void**)&mLo, g_Mlo);
    cudaGetSymbolAddress((void**)&aHi, g_Ahi);
    cudaGetSymbolAddress((void**)&aLo, g_Alo);
    cudaGetSymbolAddress((void**)&wqHi, g_WqT_hi);
    cudaGetSymbolAddress((void**)&wqLo, g_WqT_lo);
    cudaGetSymbolAddress((void**)&wpHi, g_WpT_hi);
    cudaGetSymbolAddress((void**)&wpLo, g_WpT_lo);

    cudaFuncSetAttribute(attn_mma_kernel,
                         cudaFuncAttributeMaxDynamicSharedMemorySize, ATTN_SMEM_BYTES);
    cudaFuncSetAttribute(gemm_mma_kernel,
                         cudaFuncAttributeMaxDynamicSharedMemorySize, G_SMEM_BYTES);

    // 0) Weight transpose + split, activation split (fp16 hi/lo)
    {
        dim3 blk(32, 8);
        transpose_split_kernel<<<dim3(QKV_N / 32, HID / 32), blk>>>(qkv_w, wqHi, wqLo, HID, QKV_N);
        transpose_split_kernel<<<dim3(HID / 32, HID / 32), blk>>>(proj_w, wpHi, wpLo, HID, HID);
        int n4 = ROWS * HID / 4;
        split_kernel<<<(n4 + 255) / 256, 256>>>(hidden, aHi, aLo, n4);
    }
    // 1) QKV GEMM (2-term fp16) -> split-fp16 mixed
    {
        dim3 grid(QKV_N / 128, ROWS / 128);
        gemm_mma_kernel<<<grid, 512, G_SMEM_BYTES>>>(ROWS, QKV_N, HID,
                                                     aHi, wqHi, wqLo, qkv_b,
                                                     nullptr, mHi, mLo);
    }
    // 2) FA2 HMMA attention (2-term QK^T, 2-term PV) -> split-fp16 ctx
    {
        dim3 grid(S_LEN / 128, NHEAD, BATCH);
        attn_mma_kernel<<<grid, 256, ATTN_SMEM_BYTES>>>(mHi, mLo, msk, aHi, aLo);
    }
    // 3) Projection (2-term fp16): out = ctx @ proj_w (fp32 out)
    {
        dim3 grid(HID / 128, ROWS / 128);
        gemm_mma_kernel<<<grid, 512, G_SMEM_BYTES>>>(ROWS, HID, HID,
                                                     aHi, wpHi, wpLo,
                                                     (const float*)nullptr, out,
                                                     nullptr, nullptr);
    }
    // 4) Tail: proj_bias after main output
    bias_tail_kernel<<<(HID + 255) / 256, 256>>>(proj_b, out + (size_t)ROWS * HID);
}

// round 13
// speedup vs baseline: 3.8980x; 1.1949x over previous
#include <cuda_runtime.h>
#include <cuda_fp16.h>
#include <cstdint>

// Problem constants (fixed by setup_inputs)
#define S_LEN 2048
#define BATCH 2
#define HID   2048
#define NHEAD 16
#define DHEAD 128
#define QKV_N (3 * HID)          // 6144
#define ROWS  (S_LEN * BATCH)    // 4096
#define MROW  (BATCH * QKV_N)    // 12288

// ---------------------------------------------------------------------------
// Scratch (no allocations allowed anywhere)
// ---------------------------------------------------------------------------
__device__ __half g_Mhi[(size_t)ROWS * QKV_N];     // mixed split hi
__device__ __half g_Mlo[(size_t)ROWS * QKV_N];     // mixed split lo (K cols only valid)
__device__ __half g_Ahi[(size_t)ROWS * HID];       // activation hi (hidden, then ctx)
__device__ __half g_WqT_hi[(size_t)QKV_N * HID];   // qkv_w^T [6144,2048]
__device__ __half g_WqT_lo[(size_t)QKV_N * HID];
__device__ __half g_WpT_hi[(size_t)HID * HID];     // proj_w^T [2048,2048]

// ---------------------------------------------------------------------------
// PTX helpers (sm_80-era features only — must assemble for plain sm_103)
// ---------------------------------------------------------------------------
__device__ __forceinline__ uint32_t smem_u32(const void* p) {
    uint32_t a;
    asm("{ .reg .u64 t; cvta.to.shared.u64 t, %1; cvt.u32.u64 %0, t; }"
        : "=r"(a) : "l"(p));
    return a;
}

#define CP_ASYNC16(dst, src) \
    asm volatile("cp.async.cg.shared.global [%0], [%1], 16;" \
        :: "r"(dst), "l"(src))
#define CP_COMMIT() asm volatile("cp.async.commit_group;" ::: "memory")
#define CP_WAIT1()  asm volatile("cp.async.wait_group 1;" ::: "memory")
#define CP_WAIT2()  asm volatile("cp.async.wait_group 2;" ::: "memory")

__device__ __forceinline__ void ldsm4(uint32_t* r, uint32_t addr) {
    asm volatile("ldmatrix.sync.aligned.m8n8.x4.shared.b16 {%0,%1,%2,%3}, [%4];"
        : "=r"(r[0]), "=r"(r[1]), "=r"(r[2]), "=r"(r[3]) : "r"(addr));
}
__device__ __forceinline__ void ldsm4t(uint32_t* r, uint32_t addr) {
    asm volatile("ldmatrix.sync.aligned.m8n8.x4.trans.shared.b16 {%0,%1,%2,%3}, [%4];"
        : "=r"(r[0]), "=r"(r[1]), "=r"(r[2]), "=r"(r[3]) : "r"(addr));
}

__device__ __forceinline__ void mma_f16(float* c, const uint32_t* a, const uint32_t* b) {
    asm volatile(
        "mma.sync.aligned.m16n8k16.row.col.f32.f16.f16.f32 "
        "{%0,%1,%2,%3}, {%4,%5,%6,%7}, {%8,%9}, {%0,%1,%2,%3};"
        : "+f"(c[0]), "+f"(c[1]), "+f"(c[2]), "+f"(c[3])
        : "r"(a[0]), "r"(a[1]), "r"(a[2]), "r"(a[3]), "r"(b[0]), "r"(b[1]));
}

#define SMEM_SWIZZLE_128B(o) ((o) ^ (((o) >> 3) & 0x70))
// swizzle for tiles with 256-byte rows (128 fp16)
__device__ __forceinline__ uint32_t swz256(uint32_t r, uint32_t byte) {
    return r * 256 + (byte ^ ((r & 7) << 4));
}

// fp16 hi/lo split helper
__device__ __forceinline__ void split2(float v, __half& h, __half& l) {
    h = __float2half_rn(v);
    l = __float2half_rn(v - __half2float(h));
}

// ---------------------------------------------------------------------------
// Conversion kernels
// ---------------------------------------------------------------------------
// fp32 -> fp16 hi only (lo is never consumed by the 2-term GEMMs' A operand)
__global__ void cvt_hi_kernel(const float* __restrict__ X,
                              __half* __restrict__ hi, int n4)
{
    int i = blockIdx.x * blockDim.x + threadIdx.x;
    if (i >= n4) return;
    float4 v = ((const float4*)X)[i];
    ((__half2*)hi)[i * 2]     = __halves2half2(__float2half_rn(v.x), __float2half_rn(v.y));
    ((__half2*)hi)[i * 2 + 1] = __halves2half2(__float2half_rn(v.z), __float2half_rn(v.w));
}

// W [K,N] fp32 -> hi (and optionally lo) [N,K] fp16 (transpose + split)
__global__ void transpose_split_kernel(const float* __restrict__ W,
                                       __half* __restrict__ hi,
                                       __half* __restrict__ lo,
                                       int K, int N)
{
    __shared__ float t[32][33];
    int n0 = blockIdx.x * 32, k0 = blockIdx.y * 32;
    int tx = threadIdx.x, ty = threadIdx.y;  // 32 x 8
#pragma unroll
    for (int i = 0; i < 32; i += 8)
        t[ty + i][tx] = W[(size_t)(k0 + ty + i) * N + n0 + tx];
    __syncthreads();
#pragma unroll
    for (int i = 0; i < 32; i += 8) {
        int n = n0 + ty + i;
        int k = k0 + tx;
        float v = t[tx][ty + i];   // = W[k][n]
        __half h, l;
        split2(v, h, l);
        hi[(size_t)n * K + k] = h;
        if (lo) lo[(size_t)n * K + k] = l;
    }
}

// ---------------------------------------------------------------------------
// HMMA fp16 GEMM, TERMS=2: C = Ah*(Bh+Bl) (err ~2.8e-4); TERMS=1: C = Ah*Bh.
// 512 threads / 16 warps (4x4), warp tile 32x32, BK=64, 4-stage cp.async.
// Optionally writes split-fp16 (outHi/outLo); loOnlyK=1 stores lo only for
// K-columns of the QKV layout (col%384 in [128,256)) — Q-lo/V-lo never read.
// ---------------------------------------------------------------------------
template <int TERMS>
__global__ void __launch_bounds__(512, 1)
gemm_mma_kernel(int M, int N, int K,
                const __half* __restrict__ Ahi,
                const __half* __restrict__ Bhi,
                const __half* __restrict__ Blo,
                const float* __restrict__ bias,
                float* __restrict__ C,
                __half* __restrict__ outHi,
                __half* __restrict__ outLo,
                int loOnlyK)
{
    constexpr int NTILE = 1 + TERMS;                  // tiles per stage
    constexpr uint32_t STAGE = NTILE * 16384u;
    extern __shared__ char smraw[];
    uint32_t sraw = smem_u32(smraw);
    const uint32_t sb = (sraw + 1023u) & ~1023u;

    const int tid  = threadIdx.x;
    const int lane = tid & 31;
    const int warp = tid >> 5;        // 0..15
    const int wm = warp & 3;
    const int wn = warp >> 2;
    const int rowBase = blockIdx.y * 128;
    const int colBase = blockIdx.x * 128;

    const int nch = K >> 6;           // 32

    auto load_stage = [&](int stage, int k0) {
        const uint32_t sBase = sb + stage * STAGE;
#pragma unroll
        for (int i = 0; i < NTILE * 2; i++) {
            int s = tid + i * 512;           // 0..NTILE*1024-1
            int tIdx = s >> 10;              // 0:A 1:Bhi 2:Blo
            int s2 = s & 1023;
            int r = s2 >> 3, c16 = s2 & 7;
            const __half* src = (tIdx == 0) ? Ahi : (tIdx == 1) ? Bhi : Blo;
            const int rb = (tIdx == 0) ? rowBase : colBase;
            const void* g = src + (size_t)(rb + r) * K + k0 + c16 * 8;
            CP_ASYNC16(sBase + tIdx * 16384 + SMEM_SWIZZLE_128B(r * 128 + c16 * 16), g);
        }
    };

    float c[2][4][4];
#pragma unroll
    for (int mt = 0; mt < 2; mt++)
#pragma unroll
        for (int nt = 0; nt < 4; nt++)
#pragma unroll
            for (int j = 0; j < 4; j++) c[mt][nt][j] = 0.0f;

    load_stage(0, 0);   CP_COMMIT();
    load_stage(1, 64);  CP_COMMIT();
    load_stage(2, 128); CP_COMMIT();

    const int aRow  = wm * 32 + (lane & 15);
    const int aKoff = (lane >> 4) << 4;
    const int bRow  = wn * 32 + (lane & 7) + ((lane >> 4) << 3);
    const int bKoff = ((lane >> 3) & 1) << 4;

    for (int ch = 0; ch < nch; ch++) {
        CP_WAIT2();
        __syncthreads();
        if (ch + 3 < nch) load_stage((ch + 3) & 3, (ch + 3) << 6);
        CP_COMMIT();

        const uint32_t sA  = sb + (ch & 3) * STAGE;
        const uint32_t sBh = sA + 16384;
        const uint32_t sBl = sA + 32768;

#pragma unroll
        for (int ks = 0; ks < 4; ks++) {
            uint32_t aH[2][4];
            const int kbA = ks * 32 + aKoff;
#pragma unroll
            for (int mt = 0; mt < 2; mt++) {
                uint32_t off = SMEM_SWIZZLE_128B((aRow + mt * 16) * 128 + kbA);
                ldsm4(aH[mt], sA + off);
            }
            uint32_t bH[2][4], bL[2][4];
            const int kbB = ks * 32 + bKoff;
#pragma unroll
            for (int nt = 0; nt < 2; nt++) {
                uint32_t off = SMEM_SWIZZLE_128B((bRow + nt * 16) * 128 + kbB);
                ldsm4(bH[nt], sBh + off);
                if (TERMS == 2) ldsm4(bL[nt], sBl + off);
            }
#pragma unroll
            for (int mt = 0; mt < 2; mt++)
#pragma unroll
                for (int nt = 0; nt < 2; nt++) {
                    mma_f16(c[mt][nt * 2],     aH[mt], &bH[nt][0]);
                    mma_f16(c[mt][nt * 2 + 1], aH[mt], &bH[nt][2]);
                }
            if (TERMS == 2) {
#pragma unroll
                for (int mt = 0; mt < 2; mt++)
#pragma unroll
                    for (int nt = 0; nt < 2; nt++) {
                        mma_f16(c[mt][nt * 2],     aH[mt], &bL[nt][0]);
                        mma_f16(c[mt][nt * 2 + 1], aH[mt], &bL[nt][2]);
                    }
            }
        }
    }

    const int qr = lane >> 2;
    const int qc = (lane & 3) * 2;
#pragma unroll
    for (int mt = 0; mt < 2; mt++) {
        const int row = rowBase + wm * 32 + mt * 16 + qr;
#pragma unroll
        for (int nt = 0; nt < 4; nt++) {
            const int col = colBase + wn * 32 + nt * 8 + qc;
            float b0 = 0.0f, b1 = 0.0f;
            if (bias) { b0 = bias[col]; b1 = bias[col + 1]; }
            float v00 = c[mt][nt][0] + b0, v01 = c[mt][nt][1] + b1;
            float v10 = c[mt][nt][2] + b0, v11 = c[mt][nt][3] + b1;
            if (outHi) {
                __half h00, h01, h10, h11, l00, l01, l10, l11;
                split2(v00, h00, l00); split2(v01, h01, l01);
                split2(v10, h10, l10); split2(v11, h11, l11);
                *(__half2*)&outHi[(size_t)row * N + col]       = __halves2half2(h00, h01);
                *(__half2*)&outHi[(size_t)(row + 8) * N + col] = __halves2half2(h10, h11);
                bool storeLo = true;
                if (loOnlyK) {
                    int cm = col % 384;
                    storeLo = (cm >= 128) && (cm < 256);   // K columns only
                }
                if (storeLo) {
                    *(__half2*)&outLo[(size_t)row * N + col]       = __halves2half2(l00, l01);
                    *(__half2*)&outLo[(size_t)(row + 8) * N + col] = __halves2half2(l10, l11);
                }
            } else {
                *(float2*)&C[(size_t)row * N + col]       = make_float2(v00, v01);
                *(float2*)&C[(size_t)(row + 8) * N + col] = make_float2(v10, v11);
            }
        }
    }
}

// ---------------------------------------------------------------------------
// FA2-style HMMA flash attention: 128q x 64k tiles, 8 warps x 16 rows each.
// QK^T 2-term (Qh·Kh + Qh·Kl); P·V 1-term (pH·vh). ctx written as fp16 hi.
// ---------------------------------------------------------------------------
#define A_OQH   0                     // Q hi: 32KB
#define A_OKV   32768                 // 2 stages x 48KB: KH|KL|VH (16KB each)
#define A_OMSK  131072                // 2 stages x 8KB mask
#define ATTN_SMEM_BYTES (147456 + 1024)

__global__ void __launch_bounds__(256, 1)
attn_mma_kernel(const __half* __restrict__ Mhi,
                const __half* __restrict__ Mlo,
                const unsigned char* __restrict__ mask,
                __half* __restrict__ ctxHi)
{
    extern __shared__ char smraw[];
    uint32_t sraw = smem_u32(smraw);
    const uint32_t sb = (sraw + 1023u) & ~1023u;

    const int tid  = threadIdx.x;
    const int lane = tid & 31;
    const int warp = tid >> 5;
    const int gr   = lane >> 2;
    const int qc   = (lane & 3) * 2;

    const int qt = (gridDim.x - 1) - blockIdx.x;   // heavy blocks first
    const int q0 = qt * 128;
    const int h  = blockIdx.y;
    const int b  = blockIdx.z;
    const size_t headOff = (size_t)b * QKV_N + h * (3 * DHEAD);
    const unsigned char* mb = mask + (size_t)b * S_LEN * S_LEN;

    // ---- issue Q-hi loads ----
#pragma unroll
    for (int i = 0; i < 8; i++) {
        int s = tid + i * 256;          // 0..2047
        int r = s >> 4, c16 = s & 15;
        const __half* src = Mhi + (size_t)(q0 + r) * MROW + headOff + c16 * 8;
        CP_ASYNC16(sb + A_OQH + swz256(r, c16 * 16), src);
    }
    CP_COMMIT();

    auto issue_kv = [&](int stage, int t) {
        const int k0 = t * 64;
        const uint32_t kvb = sb + A_OKV + stage * 49152;
#pragma unroll
        for (int i = 0; i < 12; i++) {
            int s = tid + i * 256;      // 0..3071
            int ts = s >> 10;           // 0:KH 1:KL 2:VH
            int s2 = s & 1023;
            int r = s2 >> 4, c16 = s2 & 15;
            const __half* src = ((ts == 1) ? Mlo : Mhi) +
                (size_t)(k0 + r) * MROW + headOff + ((ts < 2) ? DHEAD : 2 * DHEAD) + c16 * 8;
            CP_ASYNC16(kvb + ts * 16384 + swz256(r, c16 * 16), src);
        }
        const uint32_t mkb = sb + A_OMSK + stage * 8192;
#pragma unroll
        for (int i = 0; i < 2; i++) {
            int cid = tid + i * 256;
            int r = cid >> 2, c16 = cid & 3;
            const void* src = mb + (size_t)(q0 + r) * S_LEN + t * 64 + c16 * 16;
            CP_ASYNC16(mkb + r * 64 + c16 * 16, src);
        }
    };

    issue_kv(0, 0);
    CP_COMMIT();

    float accO[16][4];
#pragma unroll
    for (int nt = 0; nt < 16; nt++)
#pragma unroll
        for (int j = 0; j < 4; j++) accO[nt][j] = 0.0f;

    float m0 = -1e30f, m1 = -1e30f, l0 = 0.0f, l1 = 0.0f;
    const float scale = 0.0883883476483184405f;
    const int lr = lane & 7, mi = lane >> 3;

    const int ntiles = 2 * qt + 2;
    for (int t = 0; t < ntiles; t++) {
        const int st = t & 1;
        if (t + 1 < ntiles) issue_kv((t + 1) & 1, t + 1);
        CP_COMMIT();
        CP_WAIT1();
        __syncthreads();

        const uint32_t sKH = sb + A_OKV + st * 49152;
        const uint32_t sKL = sKH + 16384;
        const uint32_t sVH = sKH + 32768;
        const uint32_t sMsk = sb + A_OMSK + st * 8192;
        const int k0 = t * 64;

        // ================= QK^T (2-term: Qh·Kh + Qh·Kl) =================
        float s_[8][4];
#pragma unroll
        for (int nt = 0; nt < 8; nt++)
#pragma unroll
            for (int j = 0; j < 4; j++) s_[nt][j] = 0.0f;

#pragma unroll
        for (int ks = 0; ks < 8; ks++) {
            uint32_t aH[4];
            {
                uint32_t off = swz256(warp * 16 + (lane & 15),
                                      ks * 32 + ((lane >> 4) << 4));
                ldsm4(aH, sb + A_OQH + off);
            }
            uint32_t bH[4][4], bL[4][4];
            const uint32_t bByte = ks * 32 + (((lane >> 3) & 1) << 4);
#pragma unroll
            for (int p = 0; p < 4; p++) {
                uint32_t off = swz256(p * 16 + (lane & 7) + ((lane >> 4) << 3), bByte);
                ldsm4(bH[p], sKH + off);
                ldsm4(bL[p], sKL + off);
            }
#pragma unroll
            for (int p = 0; p < 4; p++) {
                mma_f16(s_[p * 2],     aH, &bH[p][0]);
                mma_f16(s_[p * 2 + 1], aH, &bH[p][2]);
            }
#pragma unroll
            for (int p = 0; p < 4; p++) {
                mma_f16(s_[p * 2],     aH, &bL[p][0]);
                mma_f16(s_[p * 2 + 1], aH, &bL[p][2]);
            }
        }

        // ---- scale + padding mask + (causal on diagonal tiles) ----
        const int r0 = q0 + warp * 16 + gr;
        const int r1 = r0 + 8;
        const bool diag = (t >= 2 * qt);
#pragma unroll
        for (int nt = 0; nt < 8; nt++) {
            const int c = nt * 8 + qc;
            unsigned short mpair0, mpair1;
            asm volatile("ld.shared.u16 %0, [%1];" : "=h"(mpair0)
                         : "r"(sMsk + (warp * 16 + gr) * 64 + c));
            asm volatile("ld.shared.u16 %0, [%1];" : "=h"(mpair1)
                         : "r"(sMsk + (warp * 16 + gr + 8) * 64 + c));
            float v0 = s_[nt][0] * scale, v1 = s_[nt][1] * scale;
            float v2 = s_[nt][2] * scale, v3 = s_[nt][3] * scale;
            if (mpair0 & 0x00FF) v0 = -10000.0f;
            if (mpair0 & 0xFF00) v1 = -10000.0f;
            if (mpair1 & 0x00FF) v2 = -10000.0f;
            if (mpair1 & 0xFF00) v3 = -10000.0f;
            if (diag) {
                if (k0 + c     > r0) v0 = -10000.0f;
                if (k0 + c + 1 > r0) v1 = -10000.0f;
                if (k0 + c     > r1) v2 = -10000.0f;
                if (k0 + c + 1 > r1) v3 = -10000.0f;
            }
            s_[nt][0] = v0; s_[nt][1] = v1; s_[nt][2] = v2; s_[nt][3] = v3;
        }

        // ---- row max (registers + quad shuffles) ----
        float mx0 = -1e30f, mx1 = -1e30f;
#pragma unroll
        for (int nt = 0; nt < 8; nt++) {
            mx0 = fmaxf(mx0, fmaxf(s_[nt][0], s_[nt][1]));
            mx1 = fmaxf(mx1, fmaxf(s_[nt][2], s_[nt][3]));
        }
        mx0 = fmaxf(mx0, __shfl_xor_sync(0xffffffffu, mx0, 1));
        mx0 = fmaxf(mx0, __shfl_xor_sync(0xffffffffu, mx0, 2));
        mx1 = fmaxf(mx1, __shfl_xor_sync(0xffffffffu, mx1, 1));
        mx1 = fmaxf(mx1, __shfl_xor_sync(0xffffffffu, mx1, 2));

        const float mn0 = fmaxf(m0, mx0);
        const float mn1 = fmaxf(m1, mx1);
        const float al0 = __expf(m0 - mn0);
        const float al1 = __expf(m1 - mn1);
        m0 = mn0; m1 = mn1;

        // ---- exp + row sums ----
        float sm0 = 0.0f, sm1 = 0.0f;
#pragma unroll
        for (int nt = 0; nt < 8; nt++) {
            float p0 = __expf(s_[nt][0] - mn0);
            float p1 = __expf(s_[nt][1] - mn0);
            float p2 = __expf(s_[nt][2] - mn1);
            float p3 = __expf(s_[nt][3] - mn1);
            sm0 += p0 + p1; sm1 += p2 + p3;
            s_[nt][0] = p0; s_[nt][1] = p1; s_[nt][2] = p2; s_[nt][3] = p3;
        }
        sm0 += __shfl_xor_sync(0xffffffffu, sm0, 1);
        sm0 += __shfl_xor_sync(0xffffffffu, sm0, 2);
        sm1 += __shfl_xor_sync(0xffffffffu, sm1, 1);
        sm1 += __shfl_xor_sync(0xffffffffu, sm1, 2);
        l0 = l0 * al0 + sm0;
        l1 = l1 * al1 + sm1;

        // ---- rescale accO ----
#pragma unroll
        for (int nt = 0; nt < 16; nt++) {
            accO[nt][0] *= al0; accO[nt][1] *= al0;
            accO[nt][2] *= al1; accO[nt][3] *= al1;
        }

        // ================= P @ V (1-term: pH·vh) =================
#pragma unroll
        for (int ks = 0; ks < 4; ks++) {
            uint32_t pH[4];
            {
                const float* e0 = s_[2 * ks];
                const float* e1 = s_[2 * ks + 1];
                __half h00 = __float2half_rn(e0[0]), h01 = __float2half_rn(e0[1]);
                __half h02 = __float2half_rn(e0[2]), h03 = __float2half_rn(e0[3]);
                __half h10 = __float2half_rn(e1[0]), h11 = __float2half_rn(e1[1]);
                __half h12 = __float2half_rn(e1[2]), h13 = __float2half_rn(e1[3]);
                __half2 a0 = __halves2half2(h00, h01);
                __half2 a1 = __halves2half2(h02, h03);
                __half2 a2 = __halves2half2(h10, h11);
                __half2 a3 = __halves2half2(h12, h13);
                pH[0] = *(uint32_t*)&a0; pH[1] = *(uint32_t*)&a1;
                pH[2] = *(uint32_t*)&a2; pH[3] = *(uint32_t*)&a3;
            }
            const uint32_t vrow = ks * 16 + ((mi & 1) << 3) + lr;
#pragma unroll
            for (int hh = 0; hh < 2; hh++) {
                uint32_t vh[4][4];
#pragma unroll
                for (int np = 0; np < 4; np++) {
                    uint32_t vbyte = (hh * 4 + np) * 32 + ((mi >> 1) << 4);
                    ldsm4t(vh[np], sVH + swz256(vrow, vbyte));
                }
                float (*aO)[4] = &accO[hh * 8];
#pragma unroll
                for (int np = 0; np < 4; np++) {
                    mma_f16(aO[np * 2],     pH, &vh[np][0]);
                    mma_f16(aO[np * 2 + 1], pH, &vh[np][2]);
                }
            }
        }
        __syncthreads();
    }

    // ---- epilogue: O/l -> fp16 ctx hi (proj GEMM A operand) ----
    const float inv0 = 1.0f / l0;
    const float inv1 = 1.0f / l1;
    const int row0 = q0 + warp * 16 + gr;
    const size_t base0 = ((size_t)row0 * BATCH + b) * HID + h * DHEAD;
    const size_t base1 = ((size_t)(row0 + 8) * BATCH + b) * HID + h * DHEAD;
#pragma unroll
    for (int nt = 0; nt < 16; nt++) {
        const int col = nt * 8 + qc;
        *(__half2*)&ctxHi[base0 + col] =
            __halves2half2(__float2half_rn(accO[nt][0] * inv0),
                           __float2half_rn(accO[nt][1] * inv0));
        *(__half2*)&ctxHi[base1 + col] =
            __halves2half2(__float2half_rn(accO[nt][2] * inv1),
                           __float2half_rn(accO[nt][3] * inv1));
    }
}

__global__ void bias_tail_kernel(const float* __restrict__ proj_bias,
                                 float* __restrict__ out_tail)
{
    int i = blockIdx.x * blockDim.x + threadIdx.x;
    if (i < HID) out_tail[i] = proj_bias[i];
}

// ---------------------------------------------------------------------------
extern "C" void kernel_launch(void* const* d_in, const int* in_sizes, int n_in,
                              void* d_out, int out_size)
{
    const float* hidden      = (const float*)d_in[0];
    const unsigned char* msk = (const unsigned char*)d_in[1];
    const float* qkv_w       = (const float*)d_in[2];
    const float* qkv_b       = (const float*)d_in[3];
    const float* proj_w      = (const float*)d_in[4];
    const float* proj_b      = (const float*)d_in[5];
    float* out               = (float*)d_out;

    __half *mHi, *mLo, *aHi, *wqHi, *wqLo, *wpHi;
    cudaGetSymbolAddress((void**)&mHi, g_Mhi);
    cudaGetSymbolAddress((void**)&mLo, g_Mlo);
    cudaGetSymbolAddress((void**)&aHi, g_Ahi);
    cudaGetSymbolAddress((void**)&wqHi, g_WqT_hi);
    cudaGetSymbolAddress((void**)&wqLo, g_WqT_lo);
    cudaGetSymbolAddress((void**)&wpHi, g_WpT_hi);

    const int gemm2_smem = 4 * 49152 + 1024;   // 197632
    const int gemm1_smem = 4 * 32768 + 1024;   // 132096
    cudaFuncSetAttribute(attn_mma_kernel,
                         cudaFuncAttributeMaxDynamicSharedMemorySize, ATTN_SMEM_BYTES);
    cudaFuncSetAttribute(gemm_mma_kernel<2>,
                         cudaFuncAttributeMaxDynamicSharedMemorySize, gemm2_smem);
    cudaFuncSetAttribute(gemm_mma_kernel<1>,
                         cudaFuncAttributeMaxDynamicSharedMemorySize, gemm1_smem);

    // 0) Weight transposes+splits; activation hi-convert
    {
        dim3 blk(32, 8);
        transpose_split_kernel<<<dim3(QKV_N / 32, HID / 32), blk>>>(qkv_w, wqHi, wqLo, HID, QKV_N);
        transpose_split_kernel<<<dim3(HID / 32, HID / 32), blk>>>(proj_w, wpHi, (__half*)nullptr, HID, HID);
        int n4 = ROWS * HID / 4;
        cvt_hi_kernel<<<(n4 + 255) / 256, 256>>>(hidden, aHi, n4);
    }
    // 1) QKV GEMM (2-term) -> split-fp16 mixed (lo only for K columns)
    {
        dim3 grid(QKV_N / 128, ROWS / 128);
        gemm_mma_kernel<2><<<grid, 512, gemm2_smem>>>(ROWS, QKV_N, HID,
                                                      aHi, wqHi, wqLo, qkv_b,
                                                      nullptr, mHi, mLo, 1);
    }
    // 2) FA2 attention (2-term QK^T, 1-term PV) -> fp16 ctx hi
    {
        dim3 grid(S_LEN / 128, NHEAD, BATCH);
        attn_mma_kernel<<<grid, 256, ATTN_SMEM_BYTES>>>(mHi, mLo, msk, aHi);
    }
    // 3) Projection (1-term): out = ctx @ proj_w (fp32 out)
    {
        dim3 grid(HID / 128, ROWS / 128);
        gemm_mma_kernel<1><<<grid, 512, gemm1_smem>>>(ROWS, HID, HID,
                                                      aHi, wpHi, (const __half*)nullptr,
                                                      (const float*)nullptr, out,
                                                      nullptr, nullptr, 0);
    }
    // 4) Tail: proj_bias after main output
    bias_tail_kernel<<<(HID + 255) / 256, 256>>>(proj_b, out + (size_t)ROWS * HID);
}

// round 17
// speedup vs baseline: 4.9433x; 1.2682x over previous
#include <cuda_runtime.h>
#include <cuda_fp16.h>
#include <cstdint>

// Problem constants (fixed by setup_inputs)
#define S_LEN 2048
#define BATCH 2
#define HID   2048
#define NHEAD 16
#define DHEAD 128
#define QKV_N (3 * HID)          // 6144
#define ROWS  (S_LEN * BATCH)    // 4096
#define MROW  (BATCH * QKV_N)    // 12288

// ---------------------------------------------------------------------------
// Scratch (no allocations allowed anywhere)
// ---------------------------------------------------------------------------
__device__ __half g_Mhi[(size_t)ROWS * QKV_N];     // mixed split hi
__device__ __half g_Mlo[(size_t)ROWS * QKV_N];     // mixed split lo (K cols only valid)
__device__ __half g_Ahi[(size_t)ROWS * HID];       // activation hi (hidden, then ctx)
__device__ __half g_WqT_hi[(size_t)QKV_N * HID];   // qkv_w^T [6144,2048]
__device__ __half g_WpT_hi[(size_t)HID * HID];     // proj_w^T [2048,2048]

// ---------------------------------------------------------------------------
// PTX helpers (sm_80-era features only — must assemble for plain sm_103)
// ---------------------------------------------------------------------------
__device__ __forceinline__ uint32_t smem_u32(const void* p) {
    uint32_t a;
    asm("{ .reg .u64 t; cvta.to.shared.u64 t, %1; cvt.u32.u64 %0, t; }"
        : "=r"(a) : "l"(p));
    return a;
}

#define CP_ASYNC16(dst, src) \
    asm volatile("cp.async.cg.shared.global [%0], [%1], 16;" \
        :: "r"(dst), "l"(src))
#define CP_COMMIT() asm volatile("cp.async.commit_group;" ::: "memory")
#define CP_WAIT1()  asm volatile("cp.async.wait_group 1;" ::: "memory")
#define CP_WAIT2()  asm volatile("cp.async.wait_group 2;" ::: "memory")

__device__ __forceinline__ void ldsm4(uint32_t* r, uint32_t addr) {
    asm volatile("ldmatrix.sync.aligned.m8n8.x4.shared.b16 {%0,%1,%2,%3}, [%4];"
        : "=r"(r[0]), "=r"(r[1]), "=r"(r[2]), "=r"(r[3]) : "r"(addr));
}
__device__ __forceinline__ void ldsm4t(uint32_t* r, uint32_t addr) {
    asm volatile("ldmatrix.sync.aligned.m8n8.x4.trans.shared.b16 {%0,%1,%2,%3}, [%4];"
        : "=r"(r[0]), "=r"(r[1]), "=r"(r[2]), "=r"(r[3]) : "r"(addr));
}

__device__ __forceinline__ void mma_f16(float* c, const uint32_t* a, const uint32_t* b) {
    asm volatile(
        "mma.sync.aligned.m16n8k16.row.col.f32.f16.f16.f32 "
        "{%0,%1,%2,%3}, {%4,%5,%6,%7}, {%8,%9}, {%0,%1,%2,%3};"
        : "+f"(c[0]), "+f"(c[1]), "+f"(c[2]), "+f"(c[3])
        : "r"(a[0]), "r"(a[1]), "r"(a[2]), "r"(a[3]), "r"(b[0]), "r"(b[1]));
}

#define SMEM_SWIZZLE_128B(o) ((o) ^ (((o) >> 3) & 0x70))
// swizzle for tiles with 256-byte rows (128 fp16)
__device__ __forceinline__ uint32_t swz256(uint32_t r, uint32_t byte) {
    return r * 256 + (byte ^ ((r & 7) << 4));
}

// fp16 hi/lo split helper
__device__ __forceinline__ void split2(float v, __half& h, __half& l) {
    h = __float2half_rn(v);
    l = __float2half_rn(v - __half2float(h));
}

// ---------------------------------------------------------------------------
// Conversion kernels
// ---------------------------------------------------------------------------
// fp32 -> fp16 hi only
__global__ void cvt_hi_kernel(const float* __restrict__ X,
                              __half* __restrict__ hi, int n4)
{
    int i = blockIdx.x * blockDim.x + threadIdx.x;
    if (i >= n4) return;
    float4 v = ((const float4*)X)[i];
    ((__half2*)hi)[i * 2]     = __halves2half2(__float2half_rn(v.x), __float2half_rn(v.y));
    ((__half2*)hi)[i * 2 + 1] = __halves2half2(__float2half_rn(v.z), __float2half_rn(v.w));
}

// W [K,N] fp32 -> hi [N,K] fp16 (transpose, hi only)
__global__ void transpose_hi_kernel(const float* __restrict__ W,
                                    __half* __restrict__ hi,
                                    int K, int N)
{
    __shared__ float t[32][33];
    int n0 = blockIdx.x * 32, k0 = blockIdx.y * 32;
    int tx = threadIdx.x, ty = threadIdx.y;  // 32 x 8
#pragma unroll
    for (int i = 0; i < 32; i += 8)
        t[ty + i][tx] = W[(size_t)(k0 + ty + i) * N + n0 + tx];
    __syncthreads();
#pragma unroll
    for (int i = 0; i < 32; i += 8) {
        int n = n0 + ty + i;
        int k = k0 + tx;
        hi[(size_t)n * K + k] = __float2half_rn(t[tx][ty + i]);
    }
}

// ---------------------------------------------------------------------------
// HMMA fp16 GEMM, TERMS=2: C = Ah*(Bh+Bl); TERMS=1: C = Ah*Bh (err ~2.8e-4).
// 512 threads / 16 warps (4x4), warp tile 32x32, BK=64, 4-stage cp.async.
// Optionally writes split-fp16 (outHi/outLo); loOnlyK=1 stores lo only for
// K-columns of the QKV layout (col%384 in [128,256)) — Q-lo/V-lo never read.
// ---------------------------------------------------------------------------
template <int TERMS>
__global__ void __launch_bounds__(512, 1)
gemm_mma_kernel(int M, int N, int K,
                const __half* __restrict__ Ahi,
                const __half* __restrict__ Bhi,
                const __half* __restrict__ Blo,
                const float* __restrict__ bias,
                float* __restrict__ C,
                __half* __restrict__ outHi,
                __half* __restrict__ outLo,
                int loOnlyK)
{
    constexpr int NTILE = 1 + TERMS;                  // tiles per stage
    constexpr uint32_t STAGE = NTILE * 16384u;
    extern __shared__ char smraw[];
    uint32_t sraw = smem_u32(smraw);
    const uint32_t sb = (sraw + 1023u) & ~1023u;

    const int tid  = threadIdx.x;
    const int lane = tid & 31;
    const int warp = tid >> 5;        // 0..15
    const int wm = warp & 3;
    const int wn = warp >> 2;
    const int rowBase = blockIdx.y * 128;
    const int colBase = blockIdx.x * 128;

    const int nch = K >> 6;           // 32

    auto load_stage = [&](int stage, int k0) {
        const uint32_t sBase = sb + stage * STAGE;
#pragma unroll
        for (int i = 0; i < NTILE * 2; i++) {
            int s = tid + i * 512;           // 0..NTILE*1024-1
            int tIdx = s >> 10;              // 0:A 1:Bhi 2:Blo
            int s2 = s & 1023;
            int r = s2 >> 3, c16 = s2 & 7;
            const __half* src = (tIdx == 0) ? Ahi : (tIdx == 1) ? Bhi : Blo;
            const int rb = (tIdx == 0) ? rowBase : colBase;
            const void* g = src + (size_t)(rb + r) * K + k0 + c16 * 8;
            CP_ASYNC16(sBase + tIdx * 16384 + SMEM_SWIZZLE_128B(r * 128 + c16 * 16), g);
        }
    };

    float c[2][4][4];
#pragma unroll
    for (int mt = 0; mt < 2; mt++)
#pragma unroll
        for (int nt = 0; nt < 4; nt++)
#pragma unroll
            for (int j = 0; j < 4; j++) c[mt][nt][j] = 0.0f;

    load_stage(0, 0);   CP_COMMIT();
    load_stage(1, 64);  CP_COMMIT();
    load_stage(2, 128); CP_COMMIT();

    const int aRow  = wm * 32 + (lane & 15);
    const int aKoff = (lane >> 4) << 4;
    const int bRow  = wn * 32 + (lane & 7) + ((lane >> 4) << 3);
    const int bKoff = ((lane >> 3) & 1) << 4;

    for (int ch = 0; ch < nch; ch++) {
        CP_WAIT2();
        __syncthreads();
        if (ch + 3 < nch) load_stage((ch + 3) & 3, (ch + 3) << 6);
        CP_COMMIT();

        const uint32_t sA  = sb + (ch & 3) * STAGE;
        const uint32_t sBh = sA + 16384;
        const uint32_t sBl = sA + 32768;

#pragma unroll
        for (int ks = 0; ks < 4; ks++) {
            uint32_t aH[2][4];
            const int kbA = ks * 32 + aKoff;
#pragma unroll
            for (int mt = 0; mt < 2; mt++) {
                uint32_t off = SMEM_SWIZZLE_128B((aRow + mt * 16) * 128 + kbA);
                ldsm4(aH[mt], sA + off);
            }
            uint32_t bH[2][4], bL[2][4];
            const int kbB = ks * 32 + bKoff;
#pragma unroll
            for (int nt = 0; nt < 2; nt++) {
                uint32_t off = SMEM_SWIZZLE_128B((bRow + nt * 16) * 128 + kbB);
                ldsm4(bH[nt], sBh + off);
                if (TERMS == 2) ldsm4(bL[nt], sBl + off);
            }
#pragma unroll
            for (int mt = 0; mt < 2; mt++)
#pragma unroll
                for (int nt = 0; nt < 2; nt++) {
                    mma_f16(c[mt][nt * 2],     aH[mt], &bH[nt][0]);
                    mma_f16(c[mt][nt * 2 + 1], aH[mt], &bH[nt][2]);
                }
            if (TERMS == 2) {
#pragma unroll
                for (int mt = 0; mt < 2; mt++)
#pragma unroll
                    for (int nt = 0; nt < 2; nt++) {
                        mma_f16(c[mt][nt * 2],     aH[mt], &bL[nt][0]);
                        mma_f16(c[mt][nt * 2 + 1], aH[mt], &bL[nt][2]);
                    }
            }
        }
    }

    const int qr = lane >> 2;
    const int qc = (lane & 3) * 2;
#pragma unroll
    for (int mt = 0; mt < 2; mt++) {
        const int row = rowBase + wm * 32 + mt * 16 + qr;
#pragma unroll
        for (int nt = 0; nt < 4; nt++) {
            const int col = colBase + wn * 32 + nt * 8 + qc;
            float b0 = 0.0f, b1 = 0.0f;
            if (bias) { b0 = bias[col]; b1 = bias[col + 1]; }
            float v00 = c[mt][nt][0] + b0, v01 = c[mt][nt][1] + b1;
            float v10 = c[mt][nt][2] + b0, v11 = c[mt][nt][3] + b1;
            if (outHi) {
                __half h00, h01, h10, h11, l00, l01, l10, l11;
                split2(v00, h00, l00); split2(v01, h01, l01);
                split2(v10, h10, l10); split2(v11, h11, l11);
                *(__half2*)&outHi[(size_t)row * N + col]       = __halves2half2(h00, h01);
                *(__half2*)&outHi[(size_t)(row + 8) * N + col] = __halves2half2(h10, h11);
                bool storeLo = true;
                if (loOnlyK) {
                    int cm = col % 384;
                    storeLo = (cm >= 128) && (cm < 256);   // K columns only
                }
                if (storeLo) {
                    *(__half2*)&outLo[(size_t)row * N + col]       = __halves2half2(l00, l01);
                    *(__half2*)&outLo[(size_t)(row + 8) * N + col] = __halves2half2(l10, l11);
                }
            } else {
                *(float2*)&C[(size_t)row * N + col]       = make_float2(v00, v01);
                *(float2*)&C[(size_t)(row + 8) * N + col] = make_float2(v10, v11);
            }
        }
    }
}

// ---------------------------------------------------------------------------
// FA2-style HMMA flash attention: 128q x 64k tiles, 8 warps x 16 rows each.
// QK^T 2-term (Qh·Kh + Qh·Kl); P·V 1-term (pH·vh). ctx written as fp16 hi.
// ---------------------------------------------------------------------------
#define A_OQH   0                     // Q hi: 32KB
#define A_OKV   32768                 // 2 stages x 48KB: KH|KL|VH (16KB each)
#define A_OMSK  131072                // 2 stages x 8KB mask
#define ATTN_SMEM_BYTES (147456 + 1024)

__global__ void __launch_bounds__(256, 1)
attn_mma_kernel(const __half* __restrict__ Mhi,
                const __half* __restrict__ Mlo,
                const unsigned char* __restrict__ mask,
                __half* __restrict__ ctxHi)
{
    extern __shared__ char smraw[];
    uint32_t sraw = smem_u32(smraw);
    const uint32_t sb = (sraw + 1023u) & ~1023u;

    const int tid  = threadIdx.x;
    const int lane = tid & 31;
    const int warp = tid >> 5;
    const int gr   = lane >> 2;
    const int qc   = (lane & 3) * 2;

    const int qt = (gridDim.x - 1) - blockIdx.x;   // heavy blocks first
    const int q0 = qt * 128;
    const int h  = blockIdx.y;
    const int b  = blockIdx.z;
    const size_t headOff = (size_t)b * QKV_N + h * (3 * DHEAD);
    const unsigned char* mb = mask + (size_t)b * S_LEN * S_LEN;

    // ---- issue Q-hi loads ----
#pragma unroll
    for (int i = 0; i < 8; i++) {
        int s = tid + i * 256;          // 0..2047
        int r = s >> 4, c16 = s & 15;
        const __half* src = Mhi + (size_t)(q0 + r) * MROW + headOff + c16 * 8;
        CP_ASYNC16(sb + A_OQH + swz256(r, c16 * 16), src);
    }
    CP_COMMIT();

    auto issue_kv = [&](int stage, int t) {
        const int k0 = t * 64;
        const uint32_t kvb = sb + A_OKV + stage * 49152;
#pragma unroll
        for (int i = 0; i < 12; i++) {
            int s = tid + i * 256;      // 0..3071
            int ts = s >> 10;           // 0:KH 1:KL 2:VH
            int s2 = s & 1023;
            int r = s2 >> 4, c16 = s2 & 15;
            const __half* src = ((ts == 1) ? Mlo : Mhi) +
                (size_t)(k0 + r) * MROW + headOff + ((ts < 2) ? DHEAD : 2 * DHEAD) + c16 * 8;
            CP_ASYNC16(kvb + ts * 16384 + swz256(r, c16 * 16), src);
        }
        const uint32_t mkb = sb + A_OMSK + stage * 8192;
#pragma unroll
        for (int i = 0; i < 2; i++) {
            int cid = tid + i * 256;
            int r = cid >> 2, c16 = cid & 3;
            const void* src = mb + (size_t)(q0 + r) * S_LEN + t * 64 + c16 * 16;
            CP_ASYNC16(mkb + r * 64 + c16 * 16, src);
        }
    };

    issue_kv(0, 0);
    CP_COMMIT();

    float accO[16][4];
#pragma unroll
    for (int nt = 0; nt < 16; nt++)
#pragma unroll
        for (int j = 0; j < 4; j++) accO[nt][j] = 0.0f;

    float m0 = -1e30f, m1 = -1e30f, l0 = 0.0f, l1 = 0.0f;
    const float scale = 0.0883883476483184405f;
    const int lr = lane & 7, mi = lane >> 3;

    const int ntiles = 2 * qt + 2;
    for (int t = 0; t < ntiles; t++) {
        const int st = t & 1;
        if (t + 1 < ntiles) issue_kv((t + 1) & 1, t + 1);
        CP_COMMIT();
        CP_WAIT1();
        __syncthreads();

        const uint32_t sKH = sb + A_OKV + st * 49152;
        const uint32_t sKL = sKH + 16384;
        const uint32_t sVH = sKH + 32768;
        const uint32_t sMsk = sb + A_OMSK + st * 8192;
        const int k0 = t * 64;

        // ================= QK^T (2-term: Qh·Kh + Qh·Kl) =================
        float s_[8][4];
#pragma unroll
        for (int nt = 0; nt < 8; nt++)
#pragma unroll
            for (int j = 0; j < 4; j++) s_[nt][j] = 0.0f;

#pragma unroll
        for (int ks = 0; ks < 8; ks++) {
            uint32_t aH[4];
            {
                uint32_t off = swz256(warp * 16 + (lane & 15),
                                      ks * 32 + ((lane >> 4) << 4));
                ldsm4(aH, sb + A_OQH + off);
            }
            uint32_t bH[4][4], bL[4][4];
            const uint32_t bByte = ks * 32 + (((lane >> 3) & 1) << 4);
#pragma unroll
            for (int p = 0; p < 4; p++) {
                uint32_t off = swz256(p * 16 + (lane & 7) + ((lane >> 4) << 3), bByte);
                ldsm4(bH[p], sKH + off);
                ldsm4(bL[p], sKL + off);
            }
#pragma unroll
            for (int p = 0; p < 4; p++) {
                mma_f16(s_[p * 2],     aH, &bH[p][0]);
                mma_f16(s_[p * 2 + 1], aH, &bH[p][2]);
            }
#pragma unroll
            for (int p = 0; p < 4; p++) {
                mma_f16(s_[p * 2],     aH, &bL[p][0]);
                mma_f16(s_[p * 2 + 1], aH, &bL[p][2]);
            }
        }

        // ---- scale + padding mask + (causal on diagonal tiles) ----
        const int r0 = q0 + warp * 16 + gr;
        const int r1 = r0 + 8;
        const bool diag = (t >= 2 * qt);
#pragma unroll
        for (int nt = 0; nt < 8; nt++) {
            const int c = nt * 8 + qc;
            unsigned short mpair0, mpair1;
            asm volatile("ld.shared.u16 %0, [%1];" : "=h"(mpair0)
                         : "r"(sMsk + (warp * 16 + gr) * 64 + c));
            asm volatile("ld.shared.u16 %0, [%1];" : "=h"(mpair1)
                         : "r"(sMsk + (warp * 16 + gr + 8) * 64 + c));
            float v0 = s_[nt][0] * scale, v1 = s_[nt][1] * scale;
            float v2 = s_[nt][2] * scale, v3 = s_[nt][3] * scale;
            if (mpair0 & 0x00FF) v0 = -10000.0f;
            if (mpair0 & 0xFF00) v1 = -10000.0f;
            if (mpair1 & 0x00FF) v2 = -10000.0f;
            if (mpair1 & 0xFF00) v3 = -10000.0f;
            if (diag) {
                if (k0 + c     > r0) v0 = -10000.0f;
                if (k0 + c + 1 > r0) v1 = -10000.0f;
                if (k0 + c     > r1) v2 = -10000.0f;
                if (k0 + c + 1 > r1) v3 = -10000.0f;
            }
            s_[nt][0] = v0; s_[nt][1] = v1; s_[nt][2] = v2; s_[nt][3] = v3;
        }

        // ---- row max (registers + quad shuffles) ----
        float mx0 = -1e30f, mx1 = -1e30f;
#pragma unroll
        for (int nt = 0; nt < 8; nt++) {
            mx0 = fmaxf(mx0, fmaxf(s_[nt][0], s_[nt][1]));
            mx1 = fmaxf(mx1, fmaxf(s_[nt][2], s_[nt][3]));
        }
        mx0 = fmaxf(mx0, __shfl_xor_sync(0xffffffffu, mx0, 1));
        mx0 = fmaxf(mx0, __shfl_xor_sync(0xffffffffu, mx0, 2));
        mx1 = fmaxf(mx1, __shfl_xor_sync(0xffffffffu, mx1, 1));
        mx1 = fmaxf(mx1, __shfl_xor_sync(0xffffffffu, mx1, 2));

        const float mn0 = fmaxf(m0, mx0);
        const float mn1 = fmaxf(m1, mx1);
        const float al0 = __expf(m0 - mn0);
        const float al1 = __expf(m1 - mn1);
        m0 = mn0; m1 = mn1;

        // ---- exp + row sums ----
        float sm0 = 0.0f, sm1 = 0.0f;
#pragma unroll
        for (int nt = 0; nt < 8; nt++) {
            float p0 = __expf(s_[nt][0] - mn0);
            float p1 = __expf(s_[nt][1] - mn0);
            float p2 = __expf(s_[nt][2] - mn1);
            float p3 = __expf(s_[nt][3] - mn1);
            sm0 += p0 + p1; sm1 += p2 + p3;
            s_[nt][0] = p0; s_[nt][1] = p1; s_[nt][2] = p2; s_[nt][3] = p3;
        }
        sm0 += __shfl_xor_sync(0xffffffffu, sm0, 1);
        sm0 += __shfl_xor_sync(0xffffffffu, sm0, 2);
        sm1 += __shfl_xor_sync(0xffffffffu, sm1, 1);
        sm1 += __shfl_xor_sync(0xffffffffu, sm1, 2);
        l0 = l0 * al0 + sm0;
        l1 = l1 * al1 + sm1;

        // ---- rescale accO ----
#pragma unroll
        for (int nt = 0; nt < 16; nt++) {
            accO[nt][0] *= al0; accO[nt][1] *= al0;
            accO[nt][2] *= al1; accO[nt][3] *= al1;
        }

        // ================= P @ V (1-term: pH·vh) =================
#pragma unroll
        for (int ks = 0; ks < 4; ks++) {
            uint32_t pH[4];
            {
                const float* e0 = s_[2 * ks];
                const float* e1 = s_[2 * ks + 1];
                __half h00 = __float2half_rn(e0[0]), h01 = __float2half_rn(e0[1]);
                __half h02 = __float2half_rn(e0[2]), h03 = __float2half_rn(e0[3]);
                __half h10 = __float2half_rn(e1[0]), h11 = __float2half_rn(e1[1]);
                __half h12 = __float2half_rn(e1[2]), h13 = __float2half_rn(e1[3]);
                __half2 a0 = __halves2half2(h00, h01);
                __half2 a1 = __halves2half2(h02, h03);
                __half2 a2 = __halves2half2(h10, h11);
                __half2 a3 = __halves2half2(h12, h13);
                pH[0] = *(uint32_t*)&a0; pH[1] = *(uint32_t*)&a1;
                pH[2] = *(uint32_t*)&a2; pH[3] = *(uint32_t*)&a3;
            }
            const uint32_t vrow = ks * 16 + ((mi & 1) << 3) + lr;
#pragma unroll
            for (int hh = 0; hh < 2; hh++) {
                uint32_t vh[4][4];
#pragma unroll
                for (int np = 0; np < 4; np++) {
                    uint32_t vbyte = (hh * 4 + np) * 32 + ((mi >> 1) << 4);
                    ldsm4t(vh[np], sVH + swz256(vrow, vbyte));
                }
                float (*aO)[4] = &accO[hh * 8];
#pragma unroll
                for (int np = 0; np < 4; np++) {
                    mma_f16(aO[np * 2],     pH, &vh[np][0]);
                    mma_f16(aO[np * 2 + 1], pH, &vh[np][2]);
                }
            }
        }
        __syncthreads();
    }

    // ---- epilogue: O/l -> fp16 ctx hi (proj GEMM A operand) ----
    const float inv0 = 1.0f / l0;
    const float inv1 = 1.0f / l1;
    const int row0 = q0 + warp * 16 + gr;
    const size_t base0 = ((size_t)row0 * BATCH + b) * HID + h * DHEAD;
    const size_t base1 = ((size_t)(row0 + 8) * BATCH + b) * HID + h * DHEAD;
#pragma unroll
    for (int nt = 0; nt < 16; nt++) {
        const int col = nt * 8 + qc;
        *(__half2*)&ctxHi[base0 + col] =
            __halves2half2(__float2half_rn(accO[nt][0] * inv0),
                           __float2half_rn(accO[nt][1] * inv0));
        *(__half2*)&ctxHi[base1 + col] =
            __halves2half2(__float2half_rn(accO[nt][2] * inv1),
                           __float2half_rn(accO[nt][3] * inv1));
    }
}

__global__ void bias_tail_kernel(const float* __restrict__ proj_bias,
                                 float* __restrict__ out_tail)
{
    int i = blockIdx.x * blockDim.x + threadIdx.x;
    if (i < HID) out_tail[i] = proj_bias[i];
}

// ---------------------------------------------------------------------------
extern "C" void kernel_launch(void* const* d_in, const int* in_sizes, int n_in,
                              void* d_out, int out_size)
{
    const float* hidden      = (const float*)d_in[0];
    const unsigned char* msk = (const unsigned char*)d_in[1];
    const float* qkv_w       = (const float*)d_in[2];
    const float* qkv_b       = (const float*)d_in[3];
    const float* proj_w      = (const float*)d_in[4];
    const float* proj_b      = (const float*)d_in[5];
    float* out               = (float*)d_out;

    __half *mHi, *mLo, *aHi, *wqHi, *wpHi;
    cudaGetSymbolAddress((void**)&mHi, g_Mhi);
    cudaGetSymbolAddress((void**)&mLo, g_Mlo);
    cudaGetSymbolAddress((void**)&aHi, g_Ahi);
    cudaGetSymbolAddress((void**)&wqHi, g_WqT_hi);
    cudaGetSymbolAddress((void**)&wpHi, g_WpT_hi);

    const int gemm1_smem = 4 * 32768 + 1024;   // 132096 (TERMS=1, 2 tiles/stage)
    cudaFuncSetAttribute(attn_mma_kernel,
                         cudaFuncAttributeMaxDynamicSharedMemorySize, ATTN_SMEM_BYTES);
    cudaFuncSetAttribute(gemm_mma_kernel<1>,
                         cudaFuncAttributeMaxDynamicSharedMemorySize, gemm1_smem);

    // 0) Weight transposes (hi only); activation hi-convert
    {
        dim3 blk(32, 8);
        transpose_hi_kernel<<<dim3(QKV_N / 32, HID / 32), blk>>>(qkv_w, wqHi, HID, QKV_N);
        transpose_hi_kernel<<<dim3(HID / 32, HID / 32), blk>>>(proj_w, wpHi, HID, HID);
        int n4 = ROWS * HID / 4;
        cvt_hi_kernel<<<(n4 + 255) / 256, 256>>>(hidden, aHi, n4);
    }
    // 1) QKV GEMM (1-term) -> split-fp16 mixed (lo only for K columns)
    {
        dim3 grid(QKV_N / 128, ROWS / 128);
        gemm_mma_kernel<1><<<grid, 512, gemm1_smem>>>(ROWS, QKV_N, HID,
                                                      aHi, wqHi, (const __half*)nullptr,
                                                      qkv_b, nullptr, mHi, mLo, 1);
    }
    // 2) FA2 attention (2-term QK^T, 1-term PV) -> fp16 ctx hi
    {
        dim3 grid(S_LEN / 128, NHEAD, BATCH);
        attn_mma_kernel<<<grid, 256, ATTN_SMEM_BYTES>>>(mHi, mLo, msk, aHi);
    }
    // 3) Projection (1-term): out = ctx @ proj_w (fp32 out)
    {
        dim3 grid(HID / 128, ROWS / 128);
        gemm_mma_kernel<1><<<grid, 512, gemm1_smem>>>(ROWS, HID, HID,
                                                      aHi, wpHi, (const __half*)nullptr,
                                                      (const float*)nullptr, out,
                                                      nullptr, nullptr, 0);
    }
    // 4) Tail: proj_bias after main output
    bias_tail_kernel<<<(HID + 255) / 256, 256>>>(proj_b, out + (size_t)ROWS * HID);
}